// round 11
// baseline (speedup 1.0000x reference)
#include <cuda_runtime.h>
#include <cuda_bf16.h>
#include <cstdint>

#define BB   2
#define CC   64
#define LL   16384
#define DIN  128
#define NST  16
#define HIDc 170
#define HID2 340
#define NCHK 256
#define CHK  64
#define HH   128
#define WW   128
#define XS2  72

// ---------------- scratch ----------------
__device__ __nv_bfloat16 g_z [BB*DIN*LL];
__device__ __nv_bfloat16 g_uc[BB*DIN*LL];
__device__ __nv_bfloat16 g_yz[BB*DIN*LL];
__device__ __nv_bfloat16 g_t [BB*HID2*LL];
__device__ __nv_bfloat16 g_gg[BB*HIDc*LL];
__device__ float g_xdbl[BB*40*LL];
__device__ float g_x1  [BB*CC*LL];
__device__ float g_chA [NCHK*BB*DIN*NST];
__device__ float g_chB [NCHK*BB*DIN*NST];
__device__ float g_h0  [NCHK*BB*DIN*NST];
__device__ float g_part1[BB*256*2];
__device__ float g_part2[BB*256*2];
__device__ float g_sc  [2*BB*CC*2];
__device__ float g_Wc  [CC*DIN];

// ---------------- helpers ----------------
__device__ __forceinline__ float siluf(float x){ return x / (1.0f + __expf(-x)); }
__device__ __forceinline__ float softplus_fast(float x){
    return (x > 20.f) ? x : __logf(1.0f + __expf(x));
}
__device__ __forceinline__ float gelu_tanh(float x){
    float x3 = x * x * x;
    float u  = 0.7978845608028654f * fmaf(0.044715f, x3, x);
    return 0.5f * x * (1.0f + tanhf(u));
}
__device__ __forceinline__ unsigned f2tf(float f){
    unsigned r;
    asm("cvt.rna.tf32.f32 %0, %1;" : "=r"(r) : "f"(f));
    return r;
}
__device__ __forceinline__ unsigned bflo(unsigned p){ return p << 16; }
__device__ __forceinline__ unsigned bfhi(unsigned p){ return p & 0xFFFF0000u; }
__device__ __forceinline__ float bflo_f(unsigned p){ return __uint_as_float(p << 16); }
__device__ __forceinline__ float bfhi_f(unsigned p){ return __uint_as_float(p & 0xFFFF0000u); }
__device__ __forceinline__ unsigned pack_bf2(float a, float b){
    __nv_bfloat162 v = __float22bfloat162_rn(make_float2(a, b));
    return *(unsigned*)&v;
}
__device__ __forceinline__ void mma4(float (&acc)[4][4], const unsigned* __restrict__ Xs,
                                     int k0, int n0, int gid, int tig,
                                     unsigned a0, unsigned a1, unsigned a2, unsigned a3){
    #pragma unroll
    for (int nt = 0; nt < 4; nt++){
        int col = n0 + nt*8 + gid;
        unsigned b0 = Xs[(k0+tig)*XS2 + col];
        unsigned b1 = Xs[(k0+tig+4)*XS2 + col];
        asm volatile("mma.sync.aligned.m16n8k8.row.col.f32.tf32.tf32.f32 "
            "{%0,%1,%2,%3}, {%4,%5,%6,%7}, {%8,%9}, {%0,%1,%2,%3};"
            : "+f"(acc[nt][0]), "+f"(acc[nt][1]), "+f"(acc[nt][2]), "+f"(acc[nt][3])
            : "r"(a0), "r"(a1), "r"(a2), "r"(a3), "r"(b0), "r"(b1));
    }
}

// ---------------- GN stats ----------------
__global__ __launch_bounds__(256) void k_stats1(const float* __restrict__ x){
    int b = blockIdx.y;
    const float* xb = x + (size_t)b*CC*LL;
    int base = blockIdx.x * 4096;
    float s = 0.f, ss = 0.f;
    for (int i = threadIdx.x; i < 4096; i += 256){
        float v = xb[base + i]; s += v; ss = fmaf(v, v, ss);
    }
    #pragma unroll
    for (int o = 16; o > 0; o >>= 1){
        s  += __shfl_down_sync(0xffffffffu, s,  o);
        ss += __shfl_down_sync(0xffffffffu, ss, o);
    }
    __shared__ float rs[8], rss[8];
    int w = threadIdx.x >> 5, ln = threadIdx.x & 31;
    if (ln == 0){ rs[w] = s; rss[w] = ss; }
    __syncthreads();
    if (threadIdx.x == 0){
        float a = 0.f, q = 0.f;
        for (int i = 0; i < 8; i++){ a += rs[i]; q += rss[i]; }
        g_part1[(b*256 + blockIdx.x)*2 + 0] = a;
        g_part1[(b*256 + blockIdx.x)*2 + 1] = q;
    }
}

__global__ __launch_bounds__(256) void k_fin(int which, const float* __restrict__ gam,
                                             const float* __restrict__ bet){
    const float* part = (which == 0) ? g_part1 : g_part2;
    int np = 256;
    int b = blockIdx.x;
    __shared__ float sh[512];
    float a = 0.f, q = 0.f;
    for (int i = threadIdx.x; i < np; i += 256){
        a += part[(b*np + i)*2 + 0];
        q += part[(b*np + i)*2 + 1];
    }
    sh[threadIdx.x] = a; sh[256 + threadIdx.x] = q;
    __syncthreads();
    for (int s = 128; s > 0; s >>= 1){
        if (threadIdx.x < s){
            sh[threadIdx.x]       += sh[threadIdx.x + s];
            sh[256 + threadIdx.x] += sh[256 + threadIdx.x + s];
        }
        __syncthreads();
    }
    if (threadIdx.x < CC){
        int c = threadIdx.x;
        float n  = (float)CC * (float)LL;
        float mu = sh[0] / n;
        float var = sh[256] / n - mu*mu;
        float rsd = rsqrtf(var + 1e-5f);
        g_sc[((which*BB + b)*CC + c)*2 + 0] = rsd * gam[c];
        g_sc[((which*BB + b)*CC + c)*2 + 1] = bet[c] - mu * rsd * gam[c];
    }
}

// ---------------- in_proj + causal conv1d + silu fused (L-tile 64) ----------------
__global__ __launch_bounds__(256) void k_inprojconv(const float* __restrict__ x,
                                                    const float* __restrict__ w,
                                                    const float* __restrict__ cw,
                                                    const float* __restrict__ cb){
    extern __shared__ char smem_raw[];
    unsigned* Xs = (unsigned*)smem_raw;                 // [64][XS2]
    float* Us = (float*)(Xs + 64*XS2);                  // [128][68]; cols 0..2 halo
    float* xh = Us + 128*68;                            // [64][4]
    int b = blockIdx.y;
    int l0 = blockIdx.x * 64;
    int tid = threadIdx.x;
    int wid = tid >> 5, lane = tid & 31;
    int gid = lane >> 2, tig = lane & 3;
    int m0 = (wid & 3) * 16, n0 = (wid >> 2) * 32;
    const float* scp = g_sc + b*CC*2;
    for (int i = tid; i < 64*64; i += 256){
        int c = i >> 6, j = i & 63;
        Xs[c*XS2 + j] = f2tf(fmaf(x[((size_t)b*CC + c)*LL + l0 + j], scp[c*2], scp[c*2+1]));
    }
    if (tid < 64*3){
        int c = tid / 3, j = tid % 3;
        float v = 0.f;
        if (l0 > 0) v = fmaf(x[((size_t)b*CC + c)*LL + l0 - 3 + j], scp[c*2], scp[c*2+1]);
        xh[c*4 + j] = v;
    }
    __syncthreads();
    if (tid < 128){
        int d = tid;
        const float* wr = w + d*64;
        float h0v = 0.f, h1v = 0.f, h2v = 0.f;
        #pragma unroll 8
        for (int c = 0; c < 64; c++){
            float wv = wr[c];
            h0v = fmaf(wv, xh[c*4 + 0], h0v);
            h1v = fmaf(wv, xh[c*4 + 1], h1v);
            h2v = fmaf(wv, xh[c*4 + 2], h2v);
        }
        Us[d*68 + 0] = h0v; Us[d*68 + 1] = h1v; Us[d*68 + 2] = h2v;
    }
    for (int og = 0; og < 4; og++){
        float acc[4][4];
        #pragma unroll
        for (int i = 0; i < 4; i++){ acc[i][0]=acc[i][1]=acc[i][2]=acc[i][3]=0.f; }
        #pragma unroll
        for (int kk = 0; kk < 8; kk++){
            int k0 = kk*8;
            const float* wr = w + (og*64 + m0 + gid)*64 + k0 + tig;
            unsigned a0 = f2tf(wr[0]);
            unsigned a1 = f2tf(wr[8*64]);
            unsigned a2 = f2tf(wr[4]);
            unsigned a3 = f2tf(wr[8*64 + 4]);
            mma4(acc, Xs, k0, n0, gid, tig, a0, a1, a2, a3);
        }
        int dbase = (og & 1) * 64;
        int r0 = dbase + m0 + gid;
        if (og >= 2){
            #pragma unroll
            for (int nt = 0; nt < 4; nt++){
                int colg = l0 + n0 + nt*8 + 2*tig;
                *(unsigned*)&g_z[((size_t)b*DIN + r0)*LL + colg]     = pack_bf2(acc[nt][0], acc[nt][1]);
                *(unsigned*)&g_z[((size_t)b*DIN + r0 + 8)*LL + colg] = pack_bf2(acc[nt][2], acc[nt][3]);
            }
        } else {
            #pragma unroll
            for (int nt = 0; nt < 4; nt++){
                int cl = n0 + nt*8 + 2*tig;
                Us[r0*68 + cl + 3]       = acc[nt][0];
                Us[r0*68 + cl + 4]       = acc[nt][1];
                Us[(r0+8)*68 + cl + 3]   = acc[nt][2];
                Us[(r0+8)*68 + cl + 4]   = acc[nt][3];
            }
        }
    }
    __syncthreads();
    // conv + silu epilogue: thread handles 4 consecutive l at fixed lq, loops 8 d
    {
        int lq = tid & 15, dgrp = tid >> 4;
        for (int k = 0; k < 8; k++){
            int d = dgrp*8 + k;
            float4 q0 = *(float4*)&Us[d*68 + 4*lq];
            float4 q1 = *(float4*)&Us[d*68 + 4*lq + 4];
            float w0 = cw[d*4+0], w1 = cw[d*4+1], w2 = cw[d*4+2], w3 = cw[d*4+3];
            float bv = cb[d];
            float y0 = fmaf(w3,q0.w, fmaf(w2,q0.z, fmaf(w1,q0.y, fmaf(w0,q0.x, bv))));
            float y1 = fmaf(w3,q1.x, fmaf(w2,q0.w, fmaf(w1,q0.z, fmaf(w0,q0.y, bv))));
            float y2 = fmaf(w3,q1.y, fmaf(w2,q1.x, fmaf(w1,q0.w, fmaf(w0,q0.z, bv))));
            float y3 = fmaf(w3,q1.z, fmaf(w2,q1.y, fmaf(w1,q1.x, fmaf(w0,q0.w, bv))));
            uint2 o;
            o.x = pack_bf2(siluf(y0), siluf(y1));
            o.y = pack_bf2(siluf(y2), siluf(y3));
            *(uint2*)&g_uc[((size_t)b*DIN + d)*LL + l0 + 4*lq] = o;
        }
    }
}

// ---------------- x_proj (36 of 64 rows valid), L-tile 64 ----------------
__global__ __launch_bounds__(256) void k_xdbl(const float* __restrict__ w){
    __shared__ unsigned Xs[32*XS2];
    int b = blockIdx.y;
    int l0 = blockIdx.x * 64;
    int tid = threadIdx.x;
    int wid = tid >> 5, lane = tid & 31;
    int gid = lane >> 2, tig = lane & 3;
    int m0 = (wid & 3) * 16, n0 = (wid >> 2) * 32;
    float acc[4][4];
    #pragma unroll
    for (int i = 0; i < 4; i++){ acc[i][0]=acc[i][1]=acc[i][2]=acc[i][3]=0.f; }
    int row0 = m0 + gid, row1 = m0 + gid + 8;
    for (int kc = 0; kc < 128; kc += 32){
        __syncthreads();
        for (int i = tid; i < 32*32; i += 256){
            int c = i >> 5, jp = (i & 31) << 1;
            unsigned pr = *(const unsigned*)&g_uc[((size_t)b*DIN + kc + c)*LL + l0 + jp];
            Xs[c*XS2 + jp]     = bflo(pr);
            Xs[c*XS2 + jp + 1] = bfhi(pr);
        }
        __syncthreads();
        #pragma unroll
        for (int kk = 0; kk < 4; kk++){
            int k0 = kk*8;
            int kcol = kc + k0 + tig;
            unsigned a0 = (row0 < 36) ? f2tf(w[row0*128 + kcol])     : 0u;
            unsigned a1 = (row1 < 36) ? f2tf(w[row1*128 + kcol])     : 0u;
            unsigned a2 = (row0 < 36) ? f2tf(w[row0*128 + kcol + 4]) : 0u;
            unsigned a3 = (row1 < 36) ? f2tf(w[row1*128 + kcol + 4]) : 0u;
            mma4(acc, Xs, k0, n0, gid, tig, a0, a1, a2, a3);
        }
    }
    #pragma unroll
    for (int nt = 0; nt < 4; nt++){
        int colg = l0 + n0 + nt*8 + 2*tig;
        if (row0 < 36)
            *(float2*)&g_xdbl[((size_t)b*40 + row0)*LL + colg] = make_float2(acc[nt][0], acc[nt][1]);
        if (row1 < 36)
            *(float2*)&g_xdbl[((size_t)b*40 + row1)*LL + colg] = make_float2(acc[nt][2], acc[nt][3]);
    }
}

// ---------------- scan (dt on the fly, float4 smem) ----------------
__global__ __launch_bounds__(128) void k_passA(const float* __restrict__ A_log,
                                               const float* __restrict__ dtw,
                                               const float* __restrict__ dtb){
    __shared__ float4 Bs4[CHK][4];
    __shared__ float4 dtr4[CHK];
    __shared__ float us [DIN][33];
    int b = blockIdx.y, chn = blockIdx.x;
    int l0 = chn * CHK;
    int tid = threadIdx.x;
    float* Bsf = (float*)Bs4;
    float* dtrf = (float*)dtr4;
    for (int idx = tid; idx < 16*CHK; idx += 128){
        int r = idx >> 6, j = idx & 63;
        Bsf[j*16 + r] = g_xdbl[((size_t)b*40 + 4 + r)*LL + l0 + j];
    }
    for (int idx = tid; idx < 4*CHK; idx += 128){
        int r = idx >> 6, j = idx & 63;
        dtrf[j*4 + r] = g_xdbl[((size_t)b*40 + r)*LL + l0 + j];
    }
    int d = tid;
    float wt0 = dtw[d*4+0], wt1 = dtw[d*4+1], wt2 = dtw[d*4+2], wt3 = dtw[d*4+3];
    float bt = dtb[d];
    float A[16], ap[16], h[16];
    float P = 1.f;
    bool pw = true;
    #pragma unroll
    for (int n = 0; n < 16; n++){
        A[n] = -__expf(A_log[d*16 + n]);
        pw = pw && (fabsf(A[n] + (float)(n+1)) < 1e-5f);
        ap[n] = 1.f; h[n] = 0.f;
    }
    for (int ts = 0; ts < CHK/32; ts++){
        __syncthreads();
        for (int idx = tid; idx < 128*16; idx += 128){
            int r = idx >> 4, jp = (idx & 15) << 1;
            unsigned pr = *(const unsigned*)&g_uc[((size_t)b*DIN + r)*LL + l0 + ts*32 + jp];
            us[r][jp]   = bflo_f(pr);
            us[r][jp+1] = bfhi_f(pr);
        }
        __syncthreads();
        if (pw){
            for (int t = 0; t < 32; t++){
                int tt = ts*32 + t;
                float4 dv = dtr4[tt];
                float v = fmaf(wt3,dv.w, fmaf(wt2,dv.z, fmaf(wt1,dv.y, fmaf(wt0,dv.x, bt))));
                float dtv = softplus_fast(v);
                float du  = dtv * us[d][t];
                float e1  = __expf(-dtv);
                P *= e1;
                float Bv[16];
                *(float4*)(Bv+ 0) = Bs4[tt][0];
                *(float4*)(Bv+ 4) = Bs4[tt][1];
                *(float4*)(Bv+ 8) = Bs4[tt][2];
                *(float4*)(Bv+12) = Bs4[tt][3];
                float a = 1.f;
                #pragma unroll
                for (int n = 0; n < 16; n++){
                    a *= e1;
                    h[n] = fmaf(a, h[n], du * Bv[n]);
                }
            }
        } else {
            for (int t = 0; t < 32; t++){
                int tt = ts*32 + t;
                float4 dv = dtr4[tt];
                float v = fmaf(wt3,dv.w, fmaf(wt2,dv.z, fmaf(wt1,dv.y, fmaf(wt0,dv.x, bt))));
                float dtv = softplus_fast(v);
                float du  = dtv * us[d][t];
                float Bv[16];
                *(float4*)(Bv+ 0) = Bs4[tt][0];
                *(float4*)(Bv+ 4) = Bs4[tt][1];
                *(float4*)(Bv+ 8) = Bs4[tt][2];
                *(float4*)(Bv+12) = Bs4[tt][3];
                #pragma unroll
                for (int n = 0; n < 16; n++){
                    float a = __expf(dtv * A[n]);
                    h[n] = fmaf(a, h[n], du * Bv[n]);
                    ap[n] *= a;
                }
            }
        }
    }
    size_t base = ((size_t)chn*BB*DIN + b*DIN + d)*16;
    if (pw){
        float a = 1.f;
        #pragma unroll
        for (int n = 0; n < 16; n++){ a *= P; g_chA[base+n] = a; g_chB[base+n] = h[n]; }
    } else {
        #pragma unroll
        for (int n = 0; n < 16; n++){ g_chA[base+n] = ap[n]; g_chB[base+n] = h[n]; }
    }
}

__global__ __launch_bounds__(64) void k_passB(){
    int i = blockIdx.x * 64 + threadIdx.x;   // over BB*DIN*NST = 4096
    float h = 0.f;
    for (int ch = 0; ch < NCHK; ch++){
        size_t idx = (size_t)ch*(BB*DIN*NST) + i;
        g_h0[idx] = h;
        h = fmaf(g_chA[idx], h, g_chB[idx]);
    }
}

__global__ __launch_bounds__(128) void k_passC(const float* __restrict__ A_log,
                                               const float* __restrict__ dtw,
                                               const float* __restrict__ dtb,
                                               const float* __restrict__ Dp){
    __shared__ float4 Bs4[CHK][4];
    __shared__ float4 Cs4[CHK][4];
    __shared__ float4 dtr4[CHK];
    __shared__ float us [DIN][17];
    __shared__ float ys [DIN][17];
    int b = blockIdx.y, chn = blockIdx.x;
    int l0 = chn * CHK;
    int tid = threadIdx.x;
    float* Bsf = (float*)Bs4;
    float* Csf = (float*)Cs4;
    float* dtrf = (float*)dtr4;
    for (int idx = tid; idx < 16*CHK; idx += 128){
        int r = idx >> 6, j = idx & 63;
        Bsf[j*16 + r] = g_xdbl[((size_t)b*40 +  4 + r)*LL + l0 + j];
        Csf[j*16 + r] = g_xdbl[((size_t)b*40 + 20 + r)*LL + l0 + j];
    }
    for (int idx = tid; idx < 4*CHK; idx += 128){
        int r = idx >> 6, j = idx & 63;
        dtrf[j*4 + r] = g_xdbl[((size_t)b*40 + r)*LL + l0 + j];
    }
    int d = tid;
    float wt0 = dtw[d*4+0], wt1 = dtw[d*4+1], wt2 = dtw[d*4+2], wt3 = dtw[d*4+3];
    float bt = dtb[d];
    float A[16], h[16];
    bool pw = true;
    size_t hbase = ((size_t)chn*BB*DIN + b*DIN + d)*16;
    #pragma unroll
    for (int n = 0; n < 16; n++){
        A[n] = -__expf(A_log[d*16 + n]);
        pw = pw && (fabsf(A[n] + (float)(n+1)) < 1e-5f);
        h[n] = g_h0[hbase + n];
    }
    float Dd = Dp[d];
    for (int ts = 0; ts < CHK/16; ts++){
        __syncthreads();
        for (int idx = tid; idx < 128*8; idx += 128){
            int r = idx >> 3, jp = (idx & 7) << 1;
            unsigned pr = *(const unsigned*)&g_uc[((size_t)b*DIN + r)*LL + l0 + ts*16 + jp];
            us[r][jp]   = bflo_f(pr);
            us[r][jp+1] = bfhi_f(pr);
        }
        __syncthreads();
        if (pw){
            for (int t = 0; t < 16; t++){
                int tt = ts*16 + t;
                float4 dv = dtr4[tt];
                float v = fmaf(wt3,dv.w, fmaf(wt2,dv.z, fmaf(wt1,dv.y, fmaf(wt0,dv.x, bt))));
                float dtv = softplus_fast(v);
                float uv = us[d][t];
                float du = dtv * uv;
                float e1 = __expf(-dtv);
                float a  = 1.f;
                float y = uv * Dd;
                float Bv[16], Cv[16];
                *(float4*)(Bv+ 0) = Bs4[tt][0];
                *(float4*)(Bv+ 4) = Bs4[tt][1];
                *(float4*)(Bv+ 8) = Bs4[tt][2];
                *(float4*)(Bv+12) = Bs4[tt][3];
                *(float4*)(Cv+ 0) = Cs4[tt][0];
                *(float4*)(Cv+ 4) = Cs4[tt][1];
                *(float4*)(Cv+ 8) = Cs4[tt][2];
                *(float4*)(Cv+12) = Cs4[tt][3];
                #pragma unroll
                for (int n = 0; n < 16; n++){
                    a *= e1;
                    h[n] = fmaf(a, h[n], du * Bv[n]);
                    y = fmaf(h[n], Cv[n], y);
                }
                ys[d][t] = y;
            }
        } else {
            for (int t = 0; t < 16; t++){
                int tt = ts*16 + t;
                float4 dv = dtr4[tt];
                float v = fmaf(wt3,dv.w, fmaf(wt2,dv.z, fmaf(wt1,dv.y, fmaf(wt0,dv.x, bt))));
                float dtv = softplus_fast(v);
                float uv = us[d][t];
                float du = dtv * uv;
                float y = uv * Dd;
                float Bv[16], Cv[16];
                *(float4*)(Bv+ 0) = Bs4[tt][0];
                *(float4*)(Bv+ 4) = Bs4[tt][1];
                *(float4*)(Bv+ 8) = Bs4[tt][2];
                *(float4*)(Bv+12) = Bs4[tt][3];
                *(float4*)(Cv+ 0) = Cs4[tt][0];
                *(float4*)(Cv+ 4) = Cs4[tt][1];
                *(float4*)(Cv+ 8) = Cs4[tt][2];
                *(float4*)(Cv+12) = Cs4[tt][3];
                #pragma unroll
                for (int n = 0; n < 16; n++){
                    float a = __expf(dtv * A[n]);
                    h[n] = fmaf(a, h[n], du * Bv[n]);
                    y = fmaf(h[n], Cv[n], y);
                }
                ys[d][t] = y;
            }
        }
        __syncthreads();
        for (int idx = tid; idx < 128*8; idx += 128){
            int r = idx >> 3, jp = (idx & 7) << 1;
            unsigned zp = *(const unsigned*)&g_z[((size_t)b*DIN + r)*LL + l0 + ts*16 + jp];
            float y0 = ys[r][jp]   * siluf(bflo_f(zp));
            float y1 = ys[r][jp+1] * siluf(bfhi_f(zp));
            *(unsigned*)&g_yz[((size_t)b*DIN + r)*LL + l0 + ts*16 + jp] = pack_bf2(y0, y1);
        }
    }
}

__global__ __launch_bounds__(256) void k_Wc(const float* __restrict__ aw,
                                            const float* __restrict__ ow){
    int i = blockIdx.x * 256 + threadIdx.x;
    if (i >= CC*DIN) return;
    int o = i >> 7, d = i & 127;
    float s = 0.f;
    for (int c = 0; c < 64; c++) s = fmaf(aw[o*64 + c], ow[c*128 + d], s);
    g_Wc[i] = s;
}

// ---------------- out_proj (+residual, +gn2 partial stats), L-tile 64 ----------------
__global__ __launch_bounds__(256) void k_outproj(const float* __restrict__ x){
    __shared__ unsigned Xs[32*XS2];
    __shared__ float rsw[8], rssw[8];
    int b = blockIdx.y;
    int l0 = blockIdx.x * 64;
    int tid = threadIdx.x;
    int wid = tid >> 5, lane = tid & 31;
    int gid = lane >> 2, tig = lane & 3;
    int m0 = (wid & 3) * 16, n0 = (wid >> 2) * 32;
    float acc[4][4];
    #pragma unroll
    for (int i = 0; i < 4; i++){ acc[i][0]=acc[i][1]=acc[i][2]=acc[i][3]=0.f; }
    int row0 = m0 + gid, row1 = m0 + gid + 8;
    for (int kc = 0; kc < 128; kc += 32){
        __syncthreads();
        for (int i = tid; i < 32*32; i += 256){
            int c = i >> 5, jp = (i & 31) << 1;
            unsigned pr = *(const unsigned*)&g_yz[((size_t)b*DIN + kc + c)*LL + l0 + jp];
            Xs[c*XS2 + jp]     = bflo(pr);
            Xs[c*XS2 + jp + 1] = bfhi(pr);
        }
        __syncthreads();
        #pragma unroll
        for (int kk = 0; kk < 4; kk++){
            int k0 = kk*8;
            int kcol = kc + k0 + tig;
            unsigned a0 = f2tf(g_Wc[row0*128 + kcol]);
            unsigned a1 = f2tf(g_Wc[row1*128 + kcol]);
            unsigned a2 = f2tf(g_Wc[row0*128 + kcol + 4]);
            unsigned a3 = f2tf(g_Wc[row1*128 + kcol + 4]);
            mma4(acc, Xs, k0, n0, gid, tig, a0, a1, a2, a3);
        }
    }
    float s = 0.f, ss = 0.f;
    #pragma unroll
    for (int nt = 0; nt < 4; nt++){
        int colg = l0 + n0 + nt*8 + 2*tig;
        float2 xr0 = *(const float2*)&x[((size_t)b*CC + row0)*LL + colg];
        float2 xr1 = *(const float2*)&x[((size_t)b*CC + row1)*LL + colg];
        float v0 = acc[nt][0] + xr0.x, v1 = acc[nt][1] + xr0.y;
        float v2 = acc[nt][2] + xr1.x, v3 = acc[nt][3] + xr1.y;
        *(float2*)&g_x1[((size_t)b*CC + row0)*LL + colg] = make_float2(v0, v1);
        *(float2*)&g_x1[((size_t)b*CC + row1)*LL + colg] = make_float2(v2, v3);
        s += v0 + v1 + v2 + v3;
        ss += v0*v0 + v1*v1 + v2*v2 + v3*v3;
    }
    #pragma unroll
    for (int o = 16; o > 0; o >>= 1){
        s  += __shfl_down_sync(0xffffffffu, s,  o);
        ss += __shfl_down_sync(0xffffffffu, ss, o);
    }
    if (lane == 0){ rsw[wid] = s; rssw[wid] = ss; }
    __syncthreads();
    if (tid == 0){
        float a = 0.f, q = 0.f;
        for (int i = 0; i < 8; i++){ a += rsw[i]; q += rssw[i]; }
        g_part2[(b*256 + blockIdx.x)*2 + 0] = a;
        g_part2[(b*256 + blockIdx.x)*2 + 1] = q;
    }
}

// ---------------- GDFN pin (t stored bf16), L-tile 64 ----------------
__global__ __launch_bounds__(256) void k_pin(const float* __restrict__ w){
    __shared__ unsigned Xs[64*XS2];
    int b = blockIdx.y;
    int l0 = blockIdx.x * 64;
    int tid = threadIdx.x;
    int wid = tid >> 5, lane = tid & 31;
    int gid = lane >> 2, tig = lane & 3;
    int m0 = (wid & 3) * 16, n0 = (wid >> 2) * 32;
    const float* scp = g_sc + (BB + b)*CC*2;
    for (int i = tid; i < 64*64; i += 256){
        int c = i >> 6, j = i & 63;
        Xs[c*XS2 + j] = f2tf(fmaf(g_x1[((size_t)b*CC + c)*LL + l0 + j], scp[c*2], scp[c*2+1]));
    }
    __syncthreads();
    for (int og = 0; og < 6; og++){
        float acc[4][4];
        #pragma unroll
        for (int i = 0; i < 4; i++){ acc[i][0]=acc[i][1]=acc[i][2]=acc[i][3]=0.f; }
        int row0 = og*64 + m0 + gid, row1 = row0 + 8;
        #pragma unroll
        for (int kk = 0; kk < 8; kk++){
            int k0 = kk*8;
            int kcol = k0 + tig;
            unsigned a0 = (row0 < HID2) ? f2tf(w[row0*64 + kcol])     : 0u;
            unsigned a1 = (row1 < HID2) ? f2tf(w[row1*64 + kcol])     : 0u;
            unsigned a2 = (row0 < HID2) ? f2tf(w[row0*64 + kcol + 4]) : 0u;
            unsigned a3 = (row1 < HID2) ? f2tf(w[row1*64 + kcol + 4]) : 0u;
            mma4(acc, Xs, k0, n0, gid, tig, a0, a1, a2, a3);
        }
        #pragma unroll
        for (int nt = 0; nt < 4; nt++){
            int colg = l0 + n0 + nt*8 + 2*tig;
            if (row0 < HID2)
                *(unsigned*)&g_t[((size_t)b*HID2 + row0)*LL + colg] = pack_bf2(acc[nt][0], acc[nt][1]);
            if (row1 < HID2)
                *(unsigned*)&g_t[((size_t)b*HID2 + row1)*LL + colg] = pack_bf2(acc[nt][2], acc[nt][3]);
        }
    }
}

__global__ void k_dw(const float* __restrict__ dww){
    __shared__ float s1[10][34], s2[10][34];
    int bc = blockIdx.z;
    int b = bc / HIDc, ch = bc % HIDc;
    int w0 = blockIdx.x * 32, h0 = blockIdx.y * 8;
    int tid = threadIdx.y * 32 + threadIdx.x;
    const __nv_bfloat16* t1 = g_t + ((size_t)b*HID2 + ch)*LL;
    const __nv_bfloat16* t2 = g_t + ((size_t)b*HID2 + ch + HIDc)*LL;
    for (int idx = tid; idx < 10*34; idx += 256){
        int hh = idx / 34 - 1 + h0, ww = idx % 34 - 1 + w0;
        bool ok = (hh >= 0 && hh < HH && ww >= 0 && ww < WW);
        s1[idx/34][idx%34] = ok ? __bfloat162float(t1[hh*WW + ww]) : 0.f;
        s2[idx/34][idx%34] = ok ? __bfloat162float(t2[hh*WW + ww]) : 0.f;
    }
    __syncthreads();
    int th = threadIdx.y, tw = threadIdx.x;
    const float* w1 = dww + ch*9;
    const float* w2 = dww + (ch + HIDc)*9;
    float a1 = 0.f, a2 = 0.f;
    #pragma unroll
    for (int dy = 0; dy < 3; dy++)
        #pragma unroll
        for (int dx = 0; dx < 3; dx++){
            a1 = fmaf(w1[dy*3+dx], s1[th+dy][tw+dx], a1);
            a2 = fmaf(w2[dy*3+dx], s2[th+dy][tw+dx], a2);
        }
    g_gg[((size_t)b*HIDc + ch)*LL + (h0+th)*WW + w0+tw] =
        __float2bfloat16_rn(gelu_tanh(a1) * a2);
}

// ---------------- pout (+residual), K=170 padded to 192, L-tile 64 ----------------
__global__ __launch_bounds__(256) void k_pout(const float* __restrict__ w,
                                              float* __restrict__ out){
    __shared__ unsigned Xs[32*XS2];
    int b = blockIdx.y;
    int l0 = blockIdx.x * 64;
    int tid = threadIdx.x;
    int wid = tid >> 5, lane = tid & 31;
    int gid = lane >> 2, tig = lane & 3;
    int m0 = (wid & 3) * 16, n0 = (wid >> 2) * 32;
    float acc[4][4];
    #pragma unroll
    for (int i = 0; i < 4; i++){ acc[i][0]=acc[i][1]=acc[i][2]=acc[i][3]=0.f; }
    int row0 = m0 + gid, row1 = m0 + gid + 8;
    for (int kc = 0; kc < 192; kc += 32){
        __syncthreads();
        for (int i = tid; i < 32*32; i += 256){
            int c = i >> 5, jp = (i & 31) << 1;
            int cg = kc + c;
            if (cg < HIDc){
                unsigned pr = *(const unsigned*)&g_gg[((size_t)b*HIDc + cg)*LL + l0 + jp];
                Xs[c*XS2 + jp]     = bflo(pr);
                Xs[c*XS2 + jp + 1] = bfhi(pr);
            } else {
                Xs[c*XS2 + jp]     = 0u;
                Xs[c*XS2 + jp + 1] = 0u;
            }
        }
        __syncthreads();
        #pragma unroll
        for (int kk = 0; kk < 4; kk++){
            int k0 = kk*8;
            int kcol = kc + k0 + tig;
            unsigned a0 = (kcol < HIDc)     ? f2tf(w[row0*HIDc + kcol])     : 0u;
            unsigned a1 = (kcol < HIDc)     ? f2tf(w[row1*HIDc + kcol])     : 0u;
            unsigned a2 = (kcol + 4 < HIDc) ? f2tf(w[row0*HIDc + kcol + 4]) : 0u;
            unsigned a3 = (kcol + 4 < HIDc) ? f2tf(w[row1*HIDc + kcol + 4]) : 0u;
            mma4(acc, Xs, k0, n0, gid, tig, a0, a1, a2, a3);
        }
    }
    #pragma unroll
    for (int nt = 0; nt < 4; nt++){
        int colg = l0 + n0 + nt*8 + 2*tig;
        float2 xr0 = *(const float2*)&g_x1[((size_t)b*CC + row0)*LL + colg];
        float2 xr1 = *(const float2*)&g_x1[((size_t)b*CC + row1)*LL + colg];
        *(float2*)&out[((size_t)b*CC + row0)*LL + colg] =
            make_float2(acc[nt][0] + xr0.x, acc[nt][1] + xr0.y);
        *(float2*)&out[((size_t)b*CC + row1)*LL + colg] =
            make_float2(acc[nt][2] + xr1.x, acc[nt][3] + xr1.y);
    }
}

extern "C" void kernel_launch(void* const* d_in, const int* in_sizes, int n_in,
                              void* d_out, int out_size){
    const float* x        = (const float*)d_in[0];
    const float* gn_a_g   = (const float*)d_in[1];
    const float* gn_a_b   = (const float*)d_in[2];
    const float* in_proj  = (const float*)d_in[3];
    const float* conv1d_w = (const float*)d_in[4];
    const float* conv1d_b = (const float*)d_in[5];
    const float* x_proj   = (const float*)d_in[6];
    const float* dt_w     = (const float*)d_in[7];
    const float* dt_b     = (const float*)d_in[8];
    const float* A_log    = (const float*)d_in[9];
    const float* D_param  = (const float*)d_in[10];
    const float* out_proj = (const float*)d_in[11];
    const float* attn_out = (const float*)d_in[12];
    const float* gn2_g    = (const float*)d_in[13];
    const float* gn2_b    = (const float*)d_in[14];
    const float* pin_w    = (const float*)d_in[15];
    const float* dw_w     = (const float*)d_in[16];
    const float* pout_w   = (const float*)d_in[17];
    float* out = (float*)d_out;

    const int SMEM_IPC = 64*XS2*4 + 128*68*4 + 64*4*4;
    cudaFuncSetAttribute(k_inprojconv, cudaFuncAttributeMaxDynamicSharedMemorySize, SMEM_IPC);

    k_stats1<<<dim3(256, BB), 256>>>(x);
    k_fin<<<BB, 256>>>(0, gn_a_g, gn_a_b);
    k_inprojconv<<<dim3(256, BB), 256, SMEM_IPC>>>(x, in_proj, conv1d_w, conv1d_b);
    k_xdbl<<<dim3(256, BB), 256>>>(x_proj);
    k_passA<<<dim3(NCHK, BB), 128>>>(A_log, dt_w, dt_b);
    k_passB<<<64, 64>>>();
    k_passC<<<dim3(NCHK, BB), 128>>>(A_log, dt_w, dt_b, D_param);
    k_Wc<<<32, 256>>>(attn_out, out_proj);
    k_outproj<<<dim3(256, BB), 256>>>(x);
    k_fin<<<BB, 256>>>(1, gn2_g, gn2_b);
    k_pin<<<dim3(256, BB), 256>>>(pin_w);
    k_dw<<<dim3(4, 16, BB*HIDc), dim3(32, 8)>>>(dw_w);
    k_pout<<<dim3(256, BB), 256>>>(pout_w, out);
}

// round 12
// speedup vs baseline: 1.0908x; 1.0908x over previous
#include <cuda_runtime.h>
#include <cuda_bf16.h>
#include <cstdint>

#define BB   2
#define CC   64
#define LL   16384
#define DIN  128
#define NST  16
#define HIDc 170
#define HID2 340
#define NCHK 256
#define CHK  64
#define HH   128
#define WW   128
#define XSTRIDE 136

// ---------------- scratch ----------------
__device__ __nv_bfloat16 g_z [BB*DIN*LL];
__device__ __nv_bfloat16 g_uc[BB*DIN*LL];
__device__ __nv_bfloat16 g_yz[BB*DIN*LL];
__device__ __nv_bfloat16 g_t [BB*HID2*LL];
__device__ __nv_bfloat16 g_gg[BB*HIDc*LL];
__device__ float g_xdbl[BB*40*LL];
__device__ float g_x1  [BB*CC*LL];
__device__ float g_chA [BB*DIN*NCHK*NST];
__device__ float g_chB [BB*DIN*NCHK*NST];
__device__ float g_h0  [BB*DIN*NCHK*NST];
__device__ float g_part1[BB*256*2];
__device__ float g_part2[BB*128*2];
__device__ float g_sc  [2*BB*CC*2];
__device__ float g_Wc  [CC*DIN];

// ---------------- helpers ----------------
__device__ __forceinline__ float siluf(float x){ return x / (1.0f + __expf(-x)); }
__device__ __forceinline__ float softplus_fast(float x){
    return (x > 20.f) ? x : __logf(1.0f + __expf(x));
}
__device__ __forceinline__ float gelu_tanh(float x){
    float x3 = x * x * x;
    float u  = 0.7978845608028654f * fmaf(0.044715f, x3, x);
    return 0.5f * x * (1.0f + tanhf(u));
}
__device__ __forceinline__ unsigned f2tf(float f){
    unsigned r;
    asm("cvt.rna.tf32.f32 %0, %1;" : "=r"(r) : "f"(f));
    return r;
}
__device__ __forceinline__ unsigned bflo(unsigned p){ return p << 16; }
__device__ __forceinline__ unsigned bfhi(unsigned p){ return p & 0xFFFF0000u; }
__device__ __forceinline__ float bflo_f(unsigned p){ return __uint_as_float(p << 16); }
__device__ __forceinline__ float bfhi_f(unsigned p){ return __uint_as_float(p & 0xFFFF0000u); }
__device__ __forceinline__ unsigned pack_bf2(float a, float b){
    __nv_bfloat162 v = __float22bfloat162_rn(make_float2(a, b));
    return *(unsigned*)&v;
}
__device__ __forceinline__ void mma8(float (&acc)[8][4], const unsigned* __restrict__ Xs,
                                     int k0, int n0, int gid, int tig,
                                     unsigned a0, unsigned a1, unsigned a2, unsigned a3){
    #pragma unroll
    for (int nt = 0; nt < 8; nt++){
        int col = n0 + nt*8 + gid;
        unsigned b0 = Xs[(k0+tig)*XSTRIDE + col];
        unsigned b1 = Xs[(k0+tig+4)*XSTRIDE + col];
        asm volatile("mma.sync.aligned.m16n8k8.row.col.f32.tf32.tf32.f32 "
            "{%0,%1,%2,%3}, {%4,%5,%6,%7}, {%8,%9}, {%0,%1,%2,%3};"
            : "+f"(acc[nt][0]), "+f"(acc[nt][1]), "+f"(acc[nt][2]), "+f"(acc[nt][3])
            : "r"(a0), "r"(a1), "r"(a2), "r"(a3), "r"(b0), "r"(b1));
    }
}

// ---------------- GN stats ----------------
__global__ __launch_bounds__(256) void k_stats1(const float* __restrict__ x){
    int b = blockIdx.y;
    const float* xb = x + (size_t)b*CC*LL;
    int base = blockIdx.x * 4096;
    float s = 0.f, ss = 0.f;
    for (int i = threadIdx.x; i < 4096; i += 256){
        float v = xb[base + i]; s += v; ss = fmaf(v, v, ss);
    }
    #pragma unroll
    for (int o = 16; o > 0; o >>= 1){
        s  += __shfl_down_sync(0xffffffffu, s,  o);
        ss += __shfl_down_sync(0xffffffffu, ss, o);
    }
    __shared__ float rs[8], rss[8];
    int w = threadIdx.x >> 5, ln = threadIdx.x & 31;
    if (ln == 0){ rs[w] = s; rss[w] = ss; }
    __syncthreads();
    if (threadIdx.x == 0){
        float a = 0.f, q = 0.f;
        for (int i = 0; i < 8; i++){ a += rs[i]; q += rss[i]; }
        g_part1[(b*256 + blockIdx.x)*2 + 0] = a;
        g_part1[(b*256 + blockIdx.x)*2 + 1] = q;
    }
}

__global__ __launch_bounds__(256) void k_fin(int which, const float* __restrict__ gam,
                                             const float* __restrict__ bet){
    const float* part = (which == 0) ? g_part1 : g_part2;
    int np = (which == 0) ? 256 : 128;
    int b = blockIdx.x;
    __shared__ float sh[512];
    float a = 0.f, q = 0.f;
    for (int i = threadIdx.x; i < np; i += 256){
        a += part[(b*np + i)*2 + 0];
        q += part[(b*np + i)*2 + 1];
    }
    sh[threadIdx.x] = a; sh[256 + threadIdx.x] = q;
    __syncthreads();
    for (int s = 128; s > 0; s >>= 1){
        if (threadIdx.x < s){
            sh[threadIdx.x]       += sh[threadIdx.x + s];
            sh[256 + threadIdx.x] += sh[256 + threadIdx.x + s];
        }
        __syncthreads();
    }
    if (threadIdx.x < CC){
        int c = threadIdx.x;
        float n  = (float)CC * (float)LL;
        float mu = sh[0] / n;
        float var = sh[256] / n - mu*mu;
        float rsd = rsqrtf(var + 1e-5f);
        g_sc[((which*BB + b)*CC + c)*2 + 0] = rsd * gam[c];
        g_sc[((which*BB + b)*CC + c)*2 + 1] = bet[c] - mu * rsd * gam[c];
    }
}

// ---------------- in_proj + causal conv1d + silu fused ----------------
__global__ __launch_bounds__(256) void k_inprojconv(const float* __restrict__ x,
                                                    const float* __restrict__ w,
                                                    const float* __restrict__ cw,
                                                    const float* __restrict__ cb){
    extern __shared__ char smem_raw[];
    unsigned* Xs = (unsigned*)smem_raw;                 // 64*XSTRIDE
    float* Us = (float*)(Xs + 64*XSTRIDE);              // [128][132]; cols 0..2 halo
    float* xh = Us + 128*132;                           // [64][4]
    int b = blockIdx.y;
    int l0 = blockIdx.x * 128;
    int tid = threadIdx.x;
    int wid = tid >> 5, lane = tid & 31;
    int gid = lane >> 2, tig = lane & 3;
    int m0 = (wid & 3) * 16, n0 = (wid >> 2) * 64;
    const float* scp = g_sc + b*CC*2;
    for (int i = tid; i < 64*128; i += 256){
        int c = i >> 7, j = i & 127;
        Xs[c*XSTRIDE + j] = f2tf(fmaf(x[((size_t)b*CC + c)*LL + l0 + j], scp[c*2], scp[c*2+1]));
    }
    if (tid < 64*3){
        int c = tid / 3, j = tid % 3;
        float v = 0.f;
        if (l0 > 0) v = fmaf(x[((size_t)b*CC + c)*LL + l0 - 3 + j], scp[c*2], scp[c*2+1]);
        xh[c*4 + j] = v;
    }
    __syncthreads();
    if (tid < 128){
        int d = tid;
        const float* wr = w + d*64;
        float h0v = 0.f, h1v = 0.f, h2v = 0.f;
        #pragma unroll 8
        for (int c = 0; c < 64; c++){
            float wv = wr[c];
            h0v = fmaf(wv, xh[c*4 + 0], h0v);
            h1v = fmaf(wv, xh[c*4 + 1], h1v);
            h2v = fmaf(wv, xh[c*4 + 2], h2v);
        }
        Us[d*132 + 0] = h0v; Us[d*132 + 1] = h1v; Us[d*132 + 2] = h2v;
    }
    for (int og = 0; og < 4; og++){
        float acc[8][4];
        #pragma unroll
        for (int i = 0; i < 8; i++){ acc[i][0]=acc[i][1]=acc[i][2]=acc[i][3]=0.f; }
        #pragma unroll
        for (int kk = 0; kk < 8; kk++){
            int k0 = kk*8;
            const float* wr = w + (og*64 + m0 + gid)*64 + k0 + tig;
            unsigned a0 = f2tf(wr[0]);
            unsigned a1 = f2tf(wr[8*64]);
            unsigned a2 = f2tf(wr[4]);
            unsigned a3 = f2tf(wr[8*64 + 4]);
            mma8(acc, Xs, k0, n0, gid, tig, a0, a1, a2, a3);
        }
        int dbase = (og & 1) * 64;
        int r0 = dbase + m0 + gid;
        if (og >= 2){
            #pragma unroll
            for (int nt = 0; nt < 8; nt++){
                int colg = l0 + n0 + nt*8 + 2*tig;
                *(unsigned*)&g_z[((size_t)b*DIN + r0)*LL + colg]     = pack_bf2(acc[nt][0], acc[nt][1]);
                *(unsigned*)&g_z[((size_t)b*DIN + r0 + 8)*LL + colg] = pack_bf2(acc[nt][2], acc[nt][3]);
            }
        } else {
            #pragma unroll
            for (int nt = 0; nt < 8; nt++){
                int cl = n0 + nt*8 + 2*tig;
                Us[r0*132 + cl + 3]       = acc[nt][0];
                Us[r0*132 + cl + 4]       = acc[nt][1];
                Us[(r0+8)*132 + cl + 3]   = acc[nt][2];
                Us[(r0+8)*132 + cl + 4]   = acc[nt][3];
            }
        }
    }
    __syncthreads();
    {
        int lq = tid & 31, dgrp = tid >> 5;
        for (int k = 0; k < 16; k++){
            int d = dgrp*16 + k;
            float4 q0 = *(float4*)&Us[d*132 + 4*lq];
            float4 q1 = *(float4*)&Us[d*132 + 4*lq + 4];
            float w0 = cw[d*4+0], w1 = cw[d*4+1], w2 = cw[d*4+2], w3 = cw[d*4+3];
            float bv = cb[d];
            float y0 = fmaf(w3,q0.w, fmaf(w2,q0.z, fmaf(w1,q0.y, fmaf(w0,q0.x, bv))));
            float y1 = fmaf(w3,q1.x, fmaf(w2,q0.w, fmaf(w1,q0.z, fmaf(w0,q0.y, bv))));
            float y2 = fmaf(w3,q1.y, fmaf(w2,q1.x, fmaf(w1,q0.w, fmaf(w0,q0.z, bv))));
            float y3 = fmaf(w3,q1.z, fmaf(w2,q1.y, fmaf(w1,q1.x, fmaf(w0,q0.w, bv))));
            uint2 o;
            o.x = pack_bf2(siluf(y0), siluf(y1));
            o.y = pack_bf2(siluf(y2), siluf(y3));
            *(uint2*)&g_uc[((size_t)b*DIN + d)*LL + l0 + 4*lq] = o;
        }
    }
}

// ---------------- x_proj, double-buffered k-chunks ----------------
__global__ __launch_bounds__(256) void k_xdbl(const float* __restrict__ w){
    __shared__ unsigned Xs[2*32*XSTRIDE];
    int b = blockIdx.y;
    int l0 = blockIdx.x * 128;
    int tid = threadIdx.x;
    int wid = tid >> 5, lane = tid & 31;
    int gid = lane >> 2, tig = lane & 3;
    int m0 = (wid & 3) * 16, n0 = (wid >> 2) * 64;
    int cth = tid >> 6;             // 0..3 (base c of this thread's 8 fill elems)
    int jpth = (tid & 63) << 1;
    float acc[8][4];
    #pragma unroll
    for (int i = 0; i < 8; i++){ acc[i][0]=acc[i][1]=acc[i][2]=acc[i][3]=0.f; }
    int row0 = m0 + gid, row1 = m0 + gid + 8;
    unsigned ld[8];
    #pragma unroll
    for (int s = 0; s < 8; s++){
        int c = cth + s*4;
        ld[s] = *(const unsigned*)&g_uc[((size_t)b*DIN + c)*LL + l0 + jpth];
    }
    int cur = 0;
    for (int kci = 0; kci < 4; kci++){
        int kc = kci*32;
        unsigned* Xb = Xs + cur*32*XSTRIDE;
        #pragma unroll
        for (int s = 0; s < 8; s++){
            int c = cth + s*4;
            Xb[c*XSTRIDE + jpth]     = bflo(ld[s]);
            Xb[c*XSTRIDE + jpth + 1] = bfhi(ld[s]);
        }
        __syncthreads();
        if (kci < 3){
            int kcn = kc + 32;
            #pragma unroll
            for (int s = 0; s < 8; s++){
                int c = cth + s*4;
                ld[s] = *(const unsigned*)&g_uc[((size_t)b*DIN + kcn + c)*LL + l0 + jpth];
            }
        }
        #pragma unroll
        for (int kk = 0; kk < 4; kk++){
            int k0 = kk*8;
            int kcol = kc + k0 + tig;
            unsigned a0 = (row0 < 36) ? f2tf(w[row0*128 + kcol])     : 0u;
            unsigned a1 = (row1 < 36) ? f2tf(w[row1*128 + kcol])     : 0u;
            unsigned a2 = (row0 < 36) ? f2tf(w[row0*128 + kcol + 4]) : 0u;
            unsigned a3 = (row1 < 36) ? f2tf(w[row1*128 + kcol + 4]) : 0u;
            mma8(acc, Xb, k0, n0, gid, tig, a0, a1, a2, a3);
        }
        cur ^= 1;
    }
    #pragma unroll
    for (int nt = 0; nt < 8; nt++){
        int colg = l0 + n0 + nt*8 + 2*tig;
        if (row0 < 36)
            *(float2*)&g_xdbl[((size_t)b*40 + row0)*LL + colg] = make_float2(acc[nt][0], acc[nt][1]);
        if (row1 < 36)
            *(float2*)&g_xdbl[((size_t)b*40 + row1)*LL + colg] = make_float2(acc[nt][2], acc[nt][3]);
    }
}

// ---------------- scan (dt on the fly, float4 smem) ----------------
__global__ __launch_bounds__(128) void k_passA(const float* __restrict__ A_log,
                                               const float* __restrict__ dtw,
                                               const float* __restrict__ dtb){
    __shared__ float4 Bs4[CHK][4];
    __shared__ float4 dtr4[CHK];
    __shared__ float us [DIN][33];
    int b = blockIdx.y, chn = blockIdx.x;
    int l0 = chn * CHK;
    int tid = threadIdx.x;
    float* Bsf = (float*)Bs4;
    float* dtrf = (float*)dtr4;
    for (int idx = tid; idx < 16*CHK; idx += 128){
        int r = idx >> 6, j = idx & 63;
        Bsf[j*16 + r] = g_xdbl[((size_t)b*40 + 4 + r)*LL + l0 + j];
    }
    for (int idx = tid; idx < 4*CHK; idx += 128){
        int r = idx >> 6, j = idx & 63;
        dtrf[j*4 + r] = g_xdbl[((size_t)b*40 + r)*LL + l0 + j];
    }
    int d = tid;
    float wt0 = dtw[d*4+0], wt1 = dtw[d*4+1], wt2 = dtw[d*4+2], wt3 = dtw[d*4+3];
    float bt = dtb[d];
    float A[16], ap[16], h[16];
    float P = 1.f;
    bool pw = true;
    #pragma unroll
    for (int n = 0; n < 16; n++){
        A[n] = -__expf(A_log[d*16 + n]);
        pw = pw && (fabsf(A[n] + (float)(n+1)) < 1e-5f);
        ap[n] = 1.f; h[n] = 0.f;
    }
    for (int ts = 0; ts < CHK/32; ts++){
        __syncthreads();
        for (int idx = tid; idx < 128*16; idx += 128){
            int r = idx >> 4, jp = (idx & 15) << 1;
            unsigned pr = *(const unsigned*)&g_uc[((size_t)b*DIN + r)*LL + l0 + ts*32 + jp];
            us[r][jp]   = bflo_f(pr);
            us[r][jp+1] = bfhi_f(pr);
        }
        __syncthreads();
        if (pw){
            for (int t = 0; t < 32; t++){
                int tt = ts*32 + t;
                float4 dv = dtr4[tt];
                float v = fmaf(wt3,dv.w, fmaf(wt2,dv.z, fmaf(wt1,dv.y, fmaf(wt0,dv.x, bt))));
                float dtv = softplus_fast(v);
                float du  = dtv * us[d][t];
                float e1  = __expf(-dtv);
                P *= e1;
                float Bv[16];
                *(float4*)(Bv+ 0) = Bs4[tt][0];
                *(float4*)(Bv+ 4) = Bs4[tt][1];
                *(float4*)(Bv+ 8) = Bs4[tt][2];
                *(float4*)(Bv+12) = Bs4[tt][3];
                float a = 1.f;
                #pragma unroll
                for (int n = 0; n < 16; n++){
                    a *= e1;
                    h[n] = fmaf(a, h[n], du * Bv[n]);
                }
            }
        } else {
            for (int t = 0; t < 32; t++){
                int tt = ts*32 + t;
                float4 dv = dtr4[tt];
                float v = fmaf(wt3,dv.w, fmaf(wt2,dv.z, fmaf(wt1,dv.y, fmaf(wt0,dv.x, bt))));
                float dtv = softplus_fast(v);
                float du  = dtv * us[d][t];
                float Bv[16];
                *(float4*)(Bv+ 0) = Bs4[tt][0];
                *(float4*)(Bv+ 4) = Bs4[tt][1];
                *(float4*)(Bv+ 8) = Bs4[tt][2];
                *(float4*)(Bv+12) = Bs4[tt][3];
                #pragma unroll
                for (int n = 0; n < 16; n++){
                    float a = __expf(dtv * A[n]);
                    h[n] = fmaf(a, h[n], du * Bv[n]);
                    ap[n] *= a;
                }
            }
        }
    }
    size_t base = (((size_t)b*DIN + d)*NCHK + chn)*16;
    if (pw){
        float a = 1.f;
        #pragma unroll
        for (int n = 0; n < 16; n++){ a *= P; g_chA[base+n] = a; g_chB[base+n] = h[n]; }
    } else {
        #pragma unroll
        for (int n = 0; n < 16; n++){ g_chA[base+n] = ap[n]; g_chB[base+n] = h[n]; }
    }
}

__global__ __launch_bounds__(256) void k_passB(){
    int i = blockIdx.x * 256 + threadIdx.x;
    if (i >= BB*DIN*NST) return;
    int n = i & 15, bd = i >> 4;
    float h = 0.f;
    size_t base = (size_t)bd*NCHK*16 + n;
    for (int ch = 0; ch < NCHK; ch++){
        size_t idx = base + (size_t)ch*16;
        g_h0[idx] = h;
        h = fmaf(g_chA[idx], h, g_chB[idx]);
    }
}

__global__ __launch_bounds__(128) void k_passC(const float* __restrict__ A_log,
                                               const float* __restrict__ dtw,
                                               const float* __restrict__ dtb,
                                               const float* __restrict__ Dp){
    __shared__ float4 Bs4[CHK][4];
    __shared__ float4 Cs4[CHK][4];
    __shared__ float4 dtr4[CHK];
    __shared__ float us [DIN][17];
    __shared__ float ys [DIN][17];
    int b = blockIdx.y, chn = blockIdx.x;
    int l0 = chn * CHK;
    int tid = threadIdx.x;
    float* Bsf = (float*)Bs4;
    float* Csf = (float*)Cs4;
    float* dtrf = (float*)dtr4;
    for (int idx = tid; idx < 16*CHK; idx += 128){
        int r = idx >> 6, j = idx & 63;
        Bsf[j*16 + r] = g_xdbl[((size_t)b*40 +  4 + r)*LL + l0 + j];
        Csf[j*16 + r] = g_xdbl[((size_t)b*40 + 20 + r)*LL + l0 + j];
    }
    for (int idx = tid; idx < 4*CHK; idx += 128){
        int r = idx >> 6, j = idx & 63;
        dtrf[j*4 + r] = g_xdbl[((size_t)b*40 + r)*LL + l0 + j];
    }
    int d = tid;
    float wt0 = dtw[d*4+0], wt1 = dtw[d*4+1], wt2 = dtw[d*4+2], wt3 = dtw[d*4+3];
    float bt = dtb[d];
    float A[16], h[16];
    bool pw = true;
    size_t hbase = (((size_t)b*DIN + d)*NCHK + chn)*16;
    #pragma unroll
    for (int n = 0; n < 16; n++){
        A[n] = -__expf(A_log[d*16 + n]);
        pw = pw && (fabsf(A[n] + (float)(n+1)) < 1e-5f);
        h[n] = g_h0[hbase + n];
    }
    float Dd = Dp[d];
    for (int ts = 0; ts < CHK/16; ts++){
        __syncthreads();
        for (int idx = tid; idx < 128*8; idx += 128){
            int r = idx >> 3, jp = (idx & 7) << 1;
            unsigned pr = *(const unsigned*)&g_uc[((size_t)b*DIN + r)*LL + l0 + ts*16 + jp];
            us[r][jp]   = bflo_f(pr);
            us[r][jp+1] = bfhi_f(pr);
        }
        __syncthreads();
        if (pw){
            for (int t = 0; t < 16; t++){
                int tt = ts*16 + t;
                float4 dv = dtr4[tt];
                float v = fmaf(wt3,dv.w, fmaf(wt2,dv.z, fmaf(wt1,dv.y, fmaf(wt0,dv.x, bt))));
                float dtv = softplus_fast(v);
                float uv = us[d][t];
                float du = dtv * uv;
                float e1 = __expf(-dtv);
                float a  = 1.f;
                float y = uv * Dd;
                float Bv[16], Cv[16];
                *(float4*)(Bv+ 0) = Bs4[tt][0];
                *(float4*)(Bv+ 4) = Bs4[tt][1];
                *(float4*)(Bv+ 8) = Bs4[tt][2];
                *(float4*)(Bv+12) = Bs4[tt][3];
                *(float4*)(Cv+ 0) = Cs4[tt][0];
                *(float4*)(Cv+ 4) = Cs4[tt][1];
                *(float4*)(Cv+ 8) = Cs4[tt][2];
                *(float4*)(Cv+12) = Cs4[tt][3];
                #pragma unroll
                for (int n = 0; n < 16; n++){
                    a *= e1;
                    h[n] = fmaf(a, h[n], du * Bv[n]);
                    y = fmaf(h[n], Cv[n], y);
                }
                ys[d][t] = y;
            }
        } else {
            for (int t = 0; t < 16; t++){
                int tt = ts*16 + t;
                float4 dv = dtr4[tt];
                float v = fmaf(wt3,dv.w, fmaf(wt2,dv.z, fmaf(wt1,dv.y, fmaf(wt0,dv.x, bt))));
                float dtv = softplus_fast(v);
                float uv = us[d][t];
                float du = dtv * uv;
                float y = uv * Dd;
                float Bv[16], Cv[16];
                *(float4*)(Bv+ 0) = Bs4[tt][0];
                *(float4*)(Bv+ 4) = Bs4[tt][1];
                *(float4*)(Bv+ 8) = Bs4[tt][2];
                *(float4*)(Bv+12) = Bs4[tt][3];
                *(float4*)(Cv+ 0) = Cs4[tt][0];
                *(float4*)(Cv+ 4) = Cs4[tt][1];
                *(float4*)(Cv+ 8) = Cs4[tt][2];
                *(float4*)(Cv+12) = Cs4[tt][3];
                #pragma unroll
                for (int n = 0; n < 16; n++){
                    float a = __expf(dtv * A[n]);
                    h[n] = fmaf(a, h[n], du * Bv[n]);
                    y = fmaf(h[n], Cv[n], y);
                }
                ys[d][t] = y;
            }
        }
        __syncthreads();
        for (int idx = tid; idx < 128*8; idx += 128){
            int r = idx >> 3, jp = (idx & 7) << 1;
            unsigned zp = *(const unsigned*)&g_z[((size_t)b*DIN + r)*LL + l0 + ts*16 + jp];
            float y0 = ys[r][jp]   * siluf(bflo_f(zp));
            float y1 = ys[r][jp+1] * siluf(bfhi_f(zp));
            *(unsigned*)&g_yz[((size_t)b*DIN + r)*LL + l0 + ts*16 + jp] = pack_bf2(y0, y1);
        }
    }
}

__global__ __launch_bounds__(256) void k_Wc(const float* __restrict__ aw,
                                            const float* __restrict__ ow){
    int i = blockIdx.x * 256 + threadIdx.x;
    if (i >= CC*DIN) return;
    int o = i >> 7, d = i & 127;
    float s = 0.f;
    for (int c = 0; c < 64; c++) s = fmaf(aw[o*64 + c], ow[c*128 + d], s);
    g_Wc[i] = s;
}

// ---------------- out_proj (+residual, +gn2 stats), double-buffered ----------------
__global__ __launch_bounds__(256) void k_outproj(const float* __restrict__ x){
    __shared__ unsigned Xs[2*32*XSTRIDE];
    __shared__ float rsw[8], rssw[8];
    int b = blockIdx.y;
    int l0 = blockIdx.x * 128;
    int tid = threadIdx.x;
    int wid = tid >> 5, lane = tid & 31;
    int gid = lane >> 2, tig = lane & 3;
    int m0 = (wid & 3) * 16, n0 = (wid >> 2) * 64;
    int cth = tid >> 6;
    int jpth = (tid & 63) << 1;
    float acc[8][4];
    #pragma unroll
    for (int i = 0; i < 8; i++){ acc[i][0]=acc[i][1]=acc[i][2]=acc[i][3]=0.f; }
    int row0 = m0 + gid, row1 = m0 + gid + 8;
    unsigned ld[8];
    #pragma unroll
    for (int s = 0; s < 8; s++){
        int c = cth + s*4;
        ld[s] = *(const unsigned*)&g_yz[((size_t)b*DIN + c)*LL + l0 + jpth];
    }
    int cur = 0;
    for (int kci = 0; kci < 4; kci++){
        int kc = kci*32;
        unsigned* Xb = Xs + cur*32*XSTRIDE;
        #pragma unroll
        for (int s = 0; s < 8; s++){
            int c = cth + s*4;
            Xb[c*XSTRIDE + jpth]     = bflo(ld[s]);
            Xb[c*XSTRIDE + jpth + 1] = bfhi(ld[s]);
        }
        __syncthreads();
        if (kci < 3){
            int kcn = kc + 32;
            #pragma unroll
            for (int s = 0; s < 8; s++){
                int c = cth + s*4;
                ld[s] = *(const unsigned*)&g_yz[((size_t)b*DIN + kcn + c)*LL + l0 + jpth];
            }
        }
        #pragma unroll
        for (int kk = 0; kk < 4; kk++){
            int k0 = kk*8;
            int kcol = kc + k0 + tig;
            unsigned a0 = f2tf(g_Wc[row0*128 + kcol]);
            unsigned a1 = f2tf(g_Wc[row1*128 + kcol]);
            unsigned a2 = f2tf(g_Wc[row0*128 + kcol + 4]);
            unsigned a3 = f2tf(g_Wc[row1*128 + kcol + 4]);
            mma8(acc, Xb, k0, n0, gid, tig, a0, a1, a2, a3);
        }
        cur ^= 1;
    }
    float s = 0.f, ss = 0.f;
    #pragma unroll
    for (int nt = 0; nt < 8; nt++){
        int colg = l0 + n0 + nt*8 + 2*tig;
        float2 xr0 = *(const float2*)&x[((size_t)b*CC + row0)*LL + colg];
        float2 xr1 = *(const float2*)&x[((size_t)b*CC + row1)*LL + colg];
        float v0 = acc[nt][0] + xr0.x, v1 = acc[nt][1] + xr0.y;
        float v2 = acc[nt][2] + xr1.x, v3 = acc[nt][3] + xr1.y;
        *(float2*)&g_x1[((size_t)b*CC + row0)*LL + colg] = make_float2(v0, v1);
        *(float2*)&g_x1[((size_t)b*CC + row1)*LL + colg] = make_float2(v2, v3);
        s += v0 + v1 + v2 + v3;
        ss += v0*v0 + v1*v1 + v2*v2 + v3*v3;
    }
    #pragma unroll
    for (int o = 16; o > 0; o >>= 1){
        s  += __shfl_down_sync(0xffffffffu, s,  o);
        ss += __shfl_down_sync(0xffffffffu, ss, o);
    }
    if (lane == 0){ rsw[wid] = s; rssw[wid] = ss; }
    __syncthreads();
    if (tid == 0){
        float a = 0.f, q = 0.f;
        for (int i = 0; i < 8; i++){ a += rsw[i]; q += rssw[i]; }
        g_part2[(b*128 + blockIdx.x)*2 + 0] = a;
        g_part2[(b*128 + blockIdx.x)*2 + 1] = q;
    }
}

// ---------------- GDFN pin (t stored bf16) ----------------
__global__ __launch_bounds__(256) void k_pin(const float* __restrict__ w){
    __shared__ unsigned Xs[64*XSTRIDE];
    int b = blockIdx.y;
    int l0 = blockIdx.x * 128;
    int tid = threadIdx.x;
    int wid = tid >> 5, lane = tid & 31;
    int gid = lane >> 2, tig = lane & 3;
    int m0 = (wid & 3) * 16, n0 = (wid >> 2) * 64;
    const float* scp = g_sc + (BB + b)*CC*2;
    for (int i = tid; i < 64*128; i += 256){
        int c = i >> 7, j = i & 127;
        Xs[c*XSTRIDE + j] = f2tf(fmaf(g_x1[((size_t)b*CC + c)*LL + l0 + j], scp[c*2], scp[c*2+1]));
    }
    __syncthreads();
    for (int og = 0; og < 6; og++){
        float acc[8][4];
        #pragma unroll
        for (int i = 0; i < 8; i++){ acc[i][0]=acc[i][1]=acc[i][2]=acc[i][3]=0.f; }
        int row0 = og*64 + m0 + gid, row1 = row0 + 8;
        #pragma unroll
        for (int kk = 0; kk < 8; kk++){
            int k0 = kk*8;
            int kcol = k0 + tig;
            unsigned a0 = (row0 < HID2) ? f2tf(w[row0*64 + kcol])     : 0u;
            unsigned a1 = (row1 < HID2) ? f2tf(w[row1*64 + kcol])     : 0u;
            unsigned a2 = (row0 < HID2) ? f2tf(w[row0*64 + kcol + 4]) : 0u;
            unsigned a3 = (row1 < HID2) ? f2tf(w[row1*64 + kcol + 4]) : 0u;
            mma8(acc, Xs, k0, n0, gid, tig, a0, a1, a2, a3);
        }
        #pragma unroll
        for (int nt = 0; nt < 8; nt++){
            int colg = l0 + n0 + nt*8 + 2*tig;
            if (row0 < HID2)
                *(unsigned*)&g_t[((size_t)b*HID2 + row0)*LL + colg] = pack_bf2(acc[nt][0], acc[nt][1]);
            if (row1 < HID2)
                *(unsigned*)&g_t[((size_t)b*HID2 + row1)*LL + colg] = pack_bf2(acc[nt][2], acc[nt][3]);
        }
    }
}

__global__ void k_dw(const float* __restrict__ dww){
    __shared__ float s1[10][34], s2[10][34];
    int bc = blockIdx.z;
    int b = bc / HIDc, ch = bc % HIDc;
    int w0 = blockIdx.x * 32, h0 = blockIdx.y * 8;
    int tid = threadIdx.y * 32 + threadIdx.x;
    const __nv_bfloat16* t1 = g_t + ((size_t)b*HID2 + ch)*LL;
    const __nv_bfloat16* t2 = g_t + ((size_t)b*HID2 + ch + HIDc)*LL;
    for (int idx = tid; idx < 10*34; idx += 256){
        int hh = idx / 34 - 1 + h0, ww = idx % 34 - 1 + w0;
        bool ok = (hh >= 0 && hh < HH && ww >= 0 && ww < WW);
        s1[idx/34][idx%34] = ok ? __bfloat162float(t1[hh*WW + ww]) : 0.f;
        s2[idx/34][idx%34] = ok ? __bfloat162float(t2[hh*WW + ww]) : 0.f;
    }
    __syncthreads();
    int th = threadIdx.y, tw = threadIdx.x;
    const float* w1 = dww + ch*9;
    const float* w2 = dww + (ch + HIDc)*9;
    float a1 = 0.f, a2 = 0.f;
    #pragma unroll
    for (int dy = 0; dy < 3; dy++)
        #pragma unroll
        for (int dx = 0; dx < 3; dx++){
            a1 = fmaf(w1[dy*3+dx], s1[th+dy][tw+dx], a1);
            a2 = fmaf(w2[dy*3+dx], s2[th+dy][tw+dx], a2);
        }
    g_gg[((size_t)b*HIDc + ch)*LL + (h0+th)*WW + w0+tw] =
        __float2bfloat16_rn(gelu_tanh(a1) * a2);
}

// ---------------- pout (+residual), K=192 padded, double-buffered ----------------
__global__ __launch_bounds__(256) void k_pout(const float* __restrict__ w,
                                              float* __restrict__ out){
    __shared__ unsigned Xs[2*32*XSTRIDE];
    int b = blockIdx.y;
    int l0 = blockIdx.x * 128;
    int tid = threadIdx.x;
    int wid = tid >> 5, lane = tid & 31;
    int gid = lane >> 2, tig = lane & 3;
    int m0 = (wid & 3) * 16, n0 = (wid >> 2) * 64;
    int cth = tid >> 6;
    int jpth = (tid & 63) << 1;
    float acc[8][4];
    #pragma unroll
    for (int i = 0; i < 8; i++){ acc[i][0]=acc[i][1]=acc[i][2]=acc[i][3]=0.f; }
    int row0 = m0 + gid, row1 = m0 + gid + 8;
    unsigned ld[8];
    #pragma unroll
    for (int s = 0; s < 8; s++){
        int cg = cth + s*4;
        ld[s] = (cg < HIDc) ? *(const unsigned*)&g_gg[((size_t)b*HIDc + cg)*LL + l0 + jpth] : 0u;
    }
    int cur = 0;
    for (int kci = 0; kci < 6; kci++){
        int kc = kci*32;
        unsigned* Xb = Xs + cur*32*XSTRIDE;
        #pragma unroll
        for (int s = 0; s < 8; s++){
            int c = cth + s*4;
            Xb[c*XSTRIDE + jpth]     = bflo(ld[s]);
            Xb[c*XSTRIDE + jpth + 1] = bfhi(ld[s]);
        }
        __syncthreads();
        if (kci < 5){
            int kcn = kc + 32;
            #pragma unroll
            for (int s = 0; s < 8; s++){
                int cg = kcn + cth + s*4;
                ld[s] = (cg < HIDc) ? *(const unsigned*)&g_gg[((size_t)b*HIDc + cg)*LL + l0 + jpth] : 0u;
            }
        }
        #pragma unroll
        for (int kk = 0; kk < 4; kk++){
            int k0 = kk*8;
            int kcol = kc + k0 + tig;
            unsigned a0 = (kcol < HIDc)     ? f2tf(w[row0*HIDc + kcol])     : 0u;
            unsigned a1 = (kcol < HIDc)     ? f2tf(w[row1*HIDc + kcol])     : 0u;
            unsigned a2 = (kcol + 4 < HIDc) ? f2tf(w[row0*HIDc + kcol + 4]) : 0u;
            unsigned a3 = (kcol + 4 < HIDc) ? f2tf(w[row1*HIDc + kcol + 4]) : 0u;
            mma8(acc, Xb, k0, n0, gid, tig, a0, a1, a2, a3);
        }
        cur ^= 1;
    }
    #pragma unroll
    for (int nt = 0; nt < 8; nt++){
        int colg = l0 + n0 + nt*8 + 2*tig;
        float2 xr0 = *(const float2*)&g_x1[((size_t)b*CC + row0)*LL + colg];
        float2 xr1 = *(const float2*)&g_x1[((size_t)b*CC + row1)*LL + colg];
        *(float2*)&out[((size_t)b*CC + row0)*LL + colg] =
            make_float2(acc[nt][0] + xr0.x, acc[nt][1] + xr0.y);
        *(float2*)&out[((size_t)b*CC + row1)*LL + colg] =
            make_float2(acc[nt][2] + xr1.x, acc[nt][3] + xr1.y);
    }
}

extern "C" void kernel_launch(void* const* d_in, const int* in_sizes, int n_in,
                              void* d_out, int out_size){
    const float* x        = (const float*)d_in[0];
    const float* gn_a_g   = (const float*)d_in[1];
    const float* gn_a_b   = (const float*)d_in[2];
    const float* in_proj  = (const float*)d_in[3];
    const float* conv1d_w = (const float*)d_in[4];
    const float* conv1d_b = (const float*)d_in[5];
    const float* x_proj   = (const float*)d_in[6];
    const float* dt_w     = (const float*)d_in[7];
    const float* dt_b     = (const float*)d_in[8];
    const float* A_log    = (const float*)d_in[9];
    const float* D_param  = (const float*)d_in[10];
    const float* out_proj = (const float*)d_in[11];
    const float* attn_out = (const float*)d_in[12];
    const float* gn2_g    = (const float*)d_in[13];
    const float* gn2_b    = (const float*)d_in[14];
    const float* pin_w    = (const float*)d_in[15];
    const float* dw_w     = (const float*)d_in[16];
    const float* pout_w   = (const float*)d_in[17];
    float* out = (float*)d_out;

    const int SMEM_IPC = 64*XSTRIDE*4 + 128*132*4 + 64*4*4;
    cudaFuncSetAttribute(k_inprojconv, cudaFuncAttributeMaxDynamicSharedMemorySize, SMEM_IPC);

    k_stats1<<<dim3(256, BB), 256>>>(x);
    k_fin<<<BB, 256>>>(0, gn_a_g, gn_a_b);
    k_inprojconv<<<dim3(128, BB), 256, SMEM_IPC>>>(x, in_proj, conv1d_w, conv1d_b);
    k_xdbl<<<dim3(128, BB), 256>>>(x_proj);
    k_passA<<<dim3(NCHK, BB), 128>>>(A_log, dt_w, dt_b);
    k_passB<<<16, 256>>>();
    k_passC<<<dim3(NCHK, BB), 128>>>(A_log, dt_w, dt_b, D_param);
    k_Wc<<<32, 256>>>(attn_out, out_proj);
    k_outproj<<<dim3(128, BB), 256>>>(x);
    k_fin<<<BB, 256>>>(1, gn2_g, gn2_b);
    k_pin<<<dim3(128, BB), 256>>>(pin_w);
    k_dw<<<dim3(4, 16, BB*HIDc), dim3(32, 8)>>>(dw_w);
    k_pout<<<dim3(128, BB), 256>>>(pout_w, out);
}

// round 13
// speedup vs baseline: 1.1095x; 1.0171x over previous
#include <cuda_runtime.h>
#include <cuda_bf16.h>
#include <cstdint>

#define BB   2
#define CC   64
#define LL   16384
#define DIN  128
#define NST  16
#define HIDc 170
#define HID2 340
#define NCHK 256
#define CHK  64
#define HH   128
#define WW   128
#define XSTRIDE 136

// ---------------- scratch ----------------
__device__ __nv_bfloat16 g_z [BB*DIN*LL];
__device__ __nv_bfloat16 g_uc[BB*DIN*LL];
__device__ __nv_bfloat16 g_yz[BB*DIN*LL];
__device__ __nv_bfloat16 g_t [BB*HID2*LL];
__device__ __nv_bfloat16 g_gg[BB*HIDc*LL];
__device__ float g_xdbl[BB*40*LL];
__device__ float g_x1  [BB*CC*LL];
__device__ float g_chA [BB*DIN*NCHK*NST];
__device__ float g_chB [BB*DIN*NCHK*NST];
__device__ float g_h0  [BB*DIN*NCHK*NST];
__device__ float g_part1[BB*256*2];
__device__ float g_part2[BB*128*2];
__device__ float g_sc  [2*BB*CC*2];
__device__ float g_Wc  [CC*DIN];

// ---------------- helpers ----------------
__device__ __forceinline__ float siluf(float x){ return x / (1.0f + __expf(-x)); }
__device__ __forceinline__ float softplus_fast(float x){
    return (x > 20.f) ? x : __logf(1.0f + __expf(x));
}
__device__ __forceinline__ float gelu_tanh(float x){
    float x3 = x * x * x;
    float u  = 0.7978845608028654f * fmaf(0.044715f, x3, x);
    float th = 1.0f - 2.0f / (__expf(2.0f * u) + 1.0f);   // tanh via MUFU exp
    return 0.5f * x * (1.0f + th);
}
__device__ __forceinline__ unsigned f2tf(float f){
    unsigned r;
    asm("cvt.rna.tf32.f32 %0, %1;" : "=r"(r) : "f"(f));
    return r;
}
__device__ __forceinline__ unsigned bflo(unsigned p){ return p << 16; }
__device__ __forceinline__ unsigned bfhi(unsigned p){ return p & 0xFFFF0000u; }
__device__ __forceinline__ float bflo_f(unsigned p){ return __uint_as_float(p << 16); }
__device__ __forceinline__ float bfhi_f(unsigned p){ return __uint_as_float(p & 0xFFFF0000u); }
__device__ __forceinline__ unsigned pack_bf2(float a, float b){
    __nv_bfloat162 v = __float22bfloat162_rn(make_float2(a, b));
    return *(unsigned*)&v;
}
__device__ __forceinline__ void mma8(float (&acc)[8][4], const unsigned* __restrict__ Xs,
                                     int k0, int n0, int gid, int tig,
                                     unsigned a0, unsigned a1, unsigned a2, unsigned a3){
    #pragma unroll
    for (int nt = 0; nt < 8; nt++){
        int col = n0 + nt*8 + gid;
        unsigned b0 = Xs[(k0+tig)*XSTRIDE + col];
        unsigned b1 = Xs[(k0+tig+4)*XSTRIDE + col];
        asm volatile("mma.sync.aligned.m16n8k8.row.col.f32.tf32.tf32.f32 "
            "{%0,%1,%2,%3}, {%4,%5,%6,%7}, {%8,%9}, {%0,%1,%2,%3};"
            : "+f"(acc[nt][0]), "+f"(acc[nt][1]), "+f"(acc[nt][2]), "+f"(acc[nt][3])
            : "r"(a0), "r"(a1), "r"(a2), "r"(a3), "r"(b0), "r"(b1));
    }
}

// ---------------- GN stats ----------------
__global__ __launch_bounds__(256) void k_stats1(const float* __restrict__ x){
    int b = blockIdx.y;
    const float* xb = x + (size_t)b*CC*LL;
    int base = blockIdx.x * 4096;
    float s = 0.f, ss = 0.f;
    for (int i = threadIdx.x; i < 4096; i += 256){
        float v = xb[base + i]; s += v; ss = fmaf(v, v, ss);
    }
    #pragma unroll
    for (int o = 16; o > 0; o >>= 1){
        s  += __shfl_down_sync(0xffffffffu, s,  o);
        ss += __shfl_down_sync(0xffffffffu, ss, o);
    }
    __shared__ float rs[8], rss[8];
    int w = threadIdx.x >> 5, ln = threadIdx.x & 31;
    if (ln == 0){ rs[w] = s; rss[w] = ss; }
    __syncthreads();
    if (threadIdx.x == 0){
        float a = 0.f, q = 0.f;
        for (int i = 0; i < 8; i++){ a += rs[i]; q += rss[i]; }
        g_part1[(b*256 + blockIdx.x)*2 + 0] = a;
        g_part1[(b*256 + blockIdx.x)*2 + 1] = q;
    }
}

__global__ __launch_bounds__(256) void k_fin(int which, const float* __restrict__ gam,
                                             const float* __restrict__ bet){
    const float* part = (which == 0) ? g_part1 : g_part2;
    int np = (which == 0) ? 256 : 128;
    int b = blockIdx.x;
    __shared__ float sh[512];
    float a = 0.f, q = 0.f;
    for (int i = threadIdx.x; i < np; i += 256){
        a += part[(b*np + i)*2 + 0];
        q += part[(b*np + i)*2 + 1];
    }
    sh[threadIdx.x] = a; sh[256 + threadIdx.x] = q;
    __syncthreads();
    for (int s = 128; s > 0; s >>= 1){
        if (threadIdx.x < s){
            sh[threadIdx.x]       += sh[threadIdx.x + s];
            sh[256 + threadIdx.x] += sh[256 + threadIdx.x + s];
        }
        __syncthreads();
    }
    if (threadIdx.x < CC){
        int c = threadIdx.x;
        float n  = (float)CC * (float)LL;
        float mu = sh[0] / n;
        float var = sh[256] / n - mu*mu;
        float rsd = rsqrtf(var + 1e-5f);
        g_sc[((which*BB + b)*CC + c)*2 + 0] = rsd * gam[c];
        g_sc[((which*BB + b)*CC + c)*2 + 1] = bet[c] - mu * rsd * gam[c];
    }
}

// ---------------- in_proj + causal conv1d + silu fused ----------------
__global__ __launch_bounds__(256) void k_inprojconv(const float* __restrict__ x,
                                                    const float* __restrict__ w,
                                                    const float* __restrict__ cw,
                                                    const float* __restrict__ cb){
    extern __shared__ char smem_raw[];
    unsigned* Xs = (unsigned*)smem_raw;
    float* Us = (float*)(Xs + 64*XSTRIDE);              // [128][132]
    float* xh = Us + 128*132;                           // [64][4]
    int b = blockIdx.y;
    int l0 = blockIdx.x * 128;
    int tid = threadIdx.x;
    int wid = tid >> 5, lane = tid & 31;
    int gid = lane >> 2, tig = lane & 3;
    int m0 = (wid & 3) * 16, n0 = (wid >> 2) * 64;
    const float* scp = g_sc + b*CC*2;
    for (int i = tid; i < 64*128; i += 256){
        int c = i >> 7, j = i & 127;
        Xs[c*XSTRIDE + j] = f2tf(fmaf(x[((size_t)b*CC + c)*LL + l0 + j], scp[c*2], scp[c*2+1]));
    }
    if (tid < 64*3){
        int c = tid / 3, j = tid % 3;
        float v = 0.f;
        if (l0 > 0) v = fmaf(x[((size_t)b*CC + c)*LL + l0 - 3 + j], scp[c*2], scp[c*2+1]);
        xh[c*4 + j] = v;
    }
    __syncthreads();
    if (tid < 128){
        int d = tid;
        const float* wr = w + d*64;
        float h0v = 0.f, h1v = 0.f, h2v = 0.f;
        #pragma unroll 8
        for (int c = 0; c < 64; c++){
            float wv = wr[c];
            h0v = fmaf(wv, xh[c*4 + 0], h0v);
            h1v = fmaf(wv, xh[c*4 + 1], h1v);
            h2v = fmaf(wv, xh[c*4 + 2], h2v);
        }
        Us[d*132 + 0] = h0v; Us[d*132 + 1] = h1v; Us[d*132 + 2] = h2v;
    }
    for (int og = 0; og < 4; og++){
        float acc[8][4];
        #pragma unroll
        for (int i = 0; i < 8; i++){ acc[i][0]=acc[i][1]=acc[i][2]=acc[i][3]=0.f; }
        #pragma unroll
        for (int kk = 0; kk < 8; kk++){
            int k0 = kk*8;
            const float* wr = w + (og*64 + m0 + gid)*64 + k0 + tig;
            unsigned a0 = f2tf(wr[0]);
            unsigned a1 = f2tf(wr[8*64]);
            unsigned a2 = f2tf(wr[4]);
            unsigned a3 = f2tf(wr[8*64 + 4]);
            mma8(acc, Xs, k0, n0, gid, tig, a0, a1, a2, a3);
        }
        int dbase = (og & 1) * 64;
        int r0 = dbase + m0 + gid;
        if (og >= 2){
            #pragma unroll
            for (int nt = 0; nt < 8; nt++){
                int colg = l0 + n0 + nt*8 + 2*tig;
                *(unsigned*)&g_z[((size_t)b*DIN + r0)*LL + colg]     = pack_bf2(acc[nt][0], acc[nt][1]);
                *(unsigned*)&g_z[((size_t)b*DIN + r0 + 8)*LL + colg] = pack_bf2(acc[nt][2], acc[nt][3]);
            }
        } else {
            #pragma unroll
            for (int nt = 0; nt < 8; nt++){
                int cl = n0 + nt*8 + 2*tig;
                Us[r0*132 + cl + 3]       = acc[nt][0];
                Us[r0*132 + cl + 4]       = acc[nt][1];
                Us[(r0+8)*132 + cl + 3]   = acc[nt][2];
                Us[(r0+8)*132 + cl + 4]   = acc[nt][3];
            }
        }
    }
    __syncthreads();
    {
        int lq = tid & 31, dgrp = tid >> 5;
        for (int k = 0; k < 16; k++){
            int d = dgrp*16 + k;
            float4 q0 = *(float4*)&Us[d*132 + 4*lq];
            float4 q1 = *(float4*)&Us[d*132 + 4*lq + 4];
            float w0 = cw[d*4+0], w1 = cw[d*4+1], w2 = cw[d*4+2], w3 = cw[d*4+3];
            float bv = cb[d];
            float y0 = fmaf(w3,q0.w, fmaf(w2,q0.z, fmaf(w1,q0.y, fmaf(w0,q0.x, bv))));
            float y1 = fmaf(w3,q1.x, fmaf(w2,q0.w, fmaf(w1,q0.z, fmaf(w0,q0.y, bv))));
            float y2 = fmaf(w3,q1.y, fmaf(w2,q1.x, fmaf(w1,q0.w, fmaf(w0,q0.z, bv))));
            float y3 = fmaf(w3,q1.z, fmaf(w2,q1.y, fmaf(w1,q1.x, fmaf(w0,q0.w, bv))));
            uint2 o;
            o.x = pack_bf2(siluf(y0), siluf(y1));
            o.y = pack_bf2(siluf(y2), siluf(y3));
            *(uint2*)&g_uc[((size_t)b*DIN + d)*LL + l0 + 4*lq] = o;
        }
    }
}

// ---------------- x_proj, double-buffered ----------------
__global__ __launch_bounds__(256) void k_xdbl(const float* __restrict__ w){
    __shared__ unsigned Xs[2*32*XSTRIDE];
    int b = blockIdx.y;
    int l0 = blockIdx.x * 128;
    int tid = threadIdx.x;
    int wid = tid >> 5, lane = tid & 31;
    int gid = lane >> 2, tig = lane & 3;
    int m0 = (wid & 3) * 16, n0 = (wid >> 2) * 64;
    int cth = tid >> 6;
    int jpth = (tid & 63) << 1;
    float acc[8][4];
    #pragma unroll
    for (int i = 0; i < 8; i++){ acc[i][0]=acc[i][1]=acc[i][2]=acc[i][3]=0.f; }
    int row0 = m0 + gid, row1 = m0 + gid + 8;
    unsigned ld[8];
    #pragma unroll
    for (int s = 0; s < 8; s++){
        int c = cth + s*4;
        ld[s] = *(const unsigned*)&g_uc[((size_t)b*DIN + c)*LL + l0 + jpth];
    }
    int cur = 0;
    for (int kci = 0; kci < 4; kci++){
        int kc = kci*32;
        unsigned* Xb = Xs + cur*32*XSTRIDE;
        #pragma unroll
        for (int s = 0; s < 8; s++){
            int c = cth + s*4;
            Xb[c*XSTRIDE + jpth]     = bflo(ld[s]);
            Xb[c*XSTRIDE + jpth + 1] = bfhi(ld[s]);
        }
        __syncthreads();
        if (kci < 3){
            int kcn = kc + 32;
            #pragma unroll
            for (int s = 0; s < 8; s++){
                int c = cth + s*4;
                ld[s] = *(const unsigned*)&g_uc[((size_t)b*DIN + kcn + c)*LL + l0 + jpth];
            }
        }
        #pragma unroll
        for (int kk = 0; kk < 4; kk++){
            int k0 = kk*8;
            int kcol = kc + k0 + tig;
            unsigned a0 = (row0 < 36) ? f2tf(w[row0*128 + kcol])     : 0u;
            unsigned a1 = (row1 < 36) ? f2tf(w[row1*128 + kcol])     : 0u;
            unsigned a2 = (row0 < 36) ? f2tf(w[row0*128 + kcol + 4]) : 0u;
            unsigned a3 = (row1 < 36) ? f2tf(w[row1*128 + kcol + 4]) : 0u;
            mma8(acc, Xb, k0, n0, gid, tig, a0, a1, a2, a3);
        }
        cur ^= 1;
    }
    #pragma unroll
    for (int nt = 0; nt < 8; nt++){
        int colg = l0 + n0 + nt*8 + 2*tig;
        if (row0 < 36)
            *(float2*)&g_xdbl[((size_t)b*40 + row0)*LL + colg] = make_float2(acc[nt][0], acc[nt][1]);
        if (row1 < 36)
            *(float2*)&g_xdbl[((size_t)b*40 + row1)*LL + colg] = make_float2(acc[nt][2], acc[nt][3]);
    }
}

// ---------------- scan passA: us prefetched into registers ----------------
__global__ __launch_bounds__(128) void k_passA(const float* __restrict__ A_log,
                                               const float* __restrict__ dtw,
                                               const float* __restrict__ dtb){
    __shared__ float4 Bs4[CHK][4];
    __shared__ float4 dtr4[CHK];
    __shared__ float us [DIN][33];
    int b = blockIdx.y, chn = blockIdx.x;
    int l0 = chn * CHK;
    int tid = threadIdx.x;
    float* Bsf = (float*)Bs4;
    float* dtrf = (float*)dtr4;
    for (int idx = tid; idx < 16*CHK; idx += 128){
        int r = idx >> 6, j = idx & 63;
        Bsf[j*16 + r] = g_xdbl[((size_t)b*40 + 4 + r)*LL + l0 + j];
    }
    for (int idx = tid; idx < 4*CHK; idx += 128){
        int r = idx >> 6, j = idx & 63;
        dtrf[j*4 + r] = g_xdbl[((size_t)b*40 + r)*LL + l0 + j];
    }
    int d = tid;
    float wt0 = dtw[d*4+0], wt1 = dtw[d*4+1], wt2 = dtw[d*4+2], wt3 = dtw[d*4+3];
    float bt = dtb[d];
    float A[16], ap[16], h[16];
    float P = 1.f;
    bool pw = true;
    #pragma unroll
    for (int n = 0; n < 16; n++){
        A[n] = -__expf(A_log[d*16 + n]);
        pw = pw && (fabsf(A[n] + (float)(n+1)) < 1e-5f);
        ap[n] = 1.f; h[n] = 0.f;
    }
    unsigned uld[16];
    #pragma unroll
    for (int s = 0; s < 16; s++){
        int idx = tid + s*128;
        int r = idx >> 4, jp = (idx & 15) << 1;
        uld[s] = *(const unsigned*)&g_uc[((size_t)b*DIN + r)*LL + l0 + jp];
    }
    for (int ts = 0; ts < CHK/32; ts++){
        __syncthreads();
        #pragma unroll
        for (int s = 0; s < 16; s++){
            int idx = tid + s*128;
            int r = idx >> 4, jp = (idx & 15) << 1;
            us[r][jp]   = bflo_f(uld[s]);
            us[r][jp+1] = bfhi_f(uld[s]);
        }
        __syncthreads();
        if (ts < CHK/32 - 1){
            #pragma unroll
            for (int s = 0; s < 16; s++){
                int idx = tid + s*128;
                int r = idx >> 4, jp = (idx & 15) << 1;
                uld[s] = *(const unsigned*)&g_uc[((size_t)b*DIN + r)*LL + l0 + (ts+1)*32 + jp];
            }
        }
        if (pw){
            for (int t = 0; t < 32; t++){
                int tt = ts*32 + t;
                float4 dv = dtr4[tt];
                float v = fmaf(wt3,dv.w, fmaf(wt2,dv.z, fmaf(wt1,dv.y, fmaf(wt0,dv.x, bt))));
                float dtv = softplus_fast(v);
                float du  = dtv * us[d][t];
                float e1  = __expf(-dtv);
                P *= e1;
                float Bv[16];
                *(float4*)(Bv+ 0) = Bs4[tt][0];
                *(float4*)(Bv+ 4) = Bs4[tt][1];
                *(float4*)(Bv+ 8) = Bs4[tt][2];
                *(float4*)(Bv+12) = Bs4[tt][3];
                float a = 1.f;
                #pragma unroll
                for (int n = 0; n < 16; n++){
                    a *= e1;
                    h[n] = fmaf(a, h[n], du * Bv[n]);
                }
            }
        } else {
            for (int t = 0; t < 32; t++){
                int tt = ts*32 + t;
                float4 dv = dtr4[tt];
                float v = fmaf(wt3,dv.w, fmaf(wt2,dv.z, fmaf(wt1,dv.y, fmaf(wt0,dv.x, bt))));
                float dtv = softplus_fast(v);
                float du  = dtv * us[d][t];
                float Bv[16];
                *(float4*)(Bv+ 0) = Bs4[tt][0];
                *(float4*)(Bv+ 4) = Bs4[tt][1];
                *(float4*)(Bv+ 8) = Bs4[tt][2];
                *(float4*)(Bv+12) = Bs4[tt][3];
                #pragma unroll
                for (int n = 0; n < 16; n++){
                    float a = __expf(dtv * A[n]);
                    h[n] = fmaf(a, h[n], du * Bv[n]);
                    ap[n] *= a;
                }
            }
        }
    }
    size_t base = (((size_t)b*DIN + d)*NCHK + chn)*16;
    if (pw){
        float a = 1.f;
        #pragma unroll
        for (int n = 0; n < 16; n++){ a *= P; g_chA[base+n] = a; g_chB[base+n] = h[n]; }
    } else {
        #pragma unroll
        for (int n = 0; n < 16; n++){ g_chA[base+n] = ap[n]; g_chB[base+n] = h[n]; }
    }
}

__global__ __launch_bounds__(64) void k_passB(){
    int i = blockIdx.x * 64 + threadIdx.x;   // over BB*DIN*NST = 4096
    int n = i & 15, bd = i >> 4;
    float h = 0.f;
    size_t base = (size_t)bd*NCHK*16 + n;
    for (int ch = 0; ch < NCHK; ch++){
        size_t idx = base + (size_t)ch*16;
        g_h0[idx] = h;
        h = fmaf(g_chA[idx], h, g_chB[idx]);
    }
}

// ---------------- scan passC: us prefetched ----------------
__global__ __launch_bounds__(128) void k_passC(const float* __restrict__ A_log,
                                               const float* __restrict__ dtw,
                                               const float* __restrict__ dtb,
                                               const float* __restrict__ Dp){
    __shared__ float4 Bs4[CHK][4];
    __shared__ float4 Cs4[CHK][4];
    __shared__ float4 dtr4[CHK];
    __shared__ float us [DIN][17];
    __shared__ float ys [DIN][17];
    int b = blockIdx.y, chn = blockIdx.x;
    int l0 = chn * CHK;
    int tid = threadIdx.x;
    float* Bsf = (float*)Bs4;
    float* Csf = (float*)Cs4;
    float* dtrf = (float*)dtr4;
    for (int idx = tid; idx < 16*CHK; idx += 128){
        int r = idx >> 6, j = idx & 63;
        Bsf[j*16 + r] = g_xdbl[((size_t)b*40 +  4 + r)*LL + l0 + j];
        Csf[j*16 + r] = g_xdbl[((size_t)b*40 + 20 + r)*LL + l0 + j];
    }
    for (int idx = tid; idx < 4*CHK; idx += 128){
        int r = idx >> 6, j = idx & 63;
        dtrf[j*4 + r] = g_xdbl[((size_t)b*40 + r)*LL + l0 + j];
    }
    int d = tid;
    float wt0 = dtw[d*4+0], wt1 = dtw[d*4+1], wt2 = dtw[d*4+2], wt3 = dtw[d*4+3];
    float bt = dtb[d];
    float A[16], h[16];
    bool pw = true;
    size_t hbase = (((size_t)b*DIN + d)*NCHK + chn)*16;
    #pragma unroll
    for (int n = 0; n < 16; n++){
        A[n] = -__expf(A_log[d*16 + n]);
        pw = pw && (fabsf(A[n] + (float)(n+1)) < 1e-5f);
        h[n] = g_h0[hbase + n];
    }
    float Dd = Dp[d];
    unsigned uld[8];
    #pragma unroll
    for (int s = 0; s < 8; s++){
        int idx = tid + s*128;
        int r = idx >> 3, jp = (idx & 7) << 1;
        uld[s] = *(const unsigned*)&g_uc[((size_t)b*DIN + r)*LL + l0 + jp];
    }
    for (int ts = 0; ts < CHK/16; ts++){
        __syncthreads();
        #pragma unroll
        for (int s = 0; s < 8; s++){
            int idx = tid + s*128;
            int r = idx >> 3, jp = (idx & 7) << 1;
            us[r][jp]   = bflo_f(uld[s]);
            us[r][jp+1] = bfhi_f(uld[s]);
        }
        __syncthreads();
        if (ts < CHK/16 - 1){
            #pragma unroll
            for (int s = 0; s < 8; s++){
                int idx = tid + s*128;
                int r = idx >> 3, jp = (idx & 7) << 1;
                uld[s] = *(const unsigned*)&g_uc[((size_t)b*DIN + r)*LL + l0 + (ts+1)*16 + jp];
            }
        }
        if (pw){
            for (int t = 0; t < 16; t++){
                int tt = ts*16 + t;
                float4 dv = dtr4[tt];
                float v = fmaf(wt3,dv.w, fmaf(wt2,dv.z, fmaf(wt1,dv.y, fmaf(wt0,dv.x, bt))));
                float dtv = softplus_fast(v);
                float uv = us[d][t];
                float du = dtv * uv;
                float e1 = __expf(-dtv);
                float a  = 1.f;
                float y = uv * Dd;
                float Bv[16], Cv[16];
                *(float4*)(Bv+ 0) = Bs4[tt][0];
                *(float4*)(Bv+ 4) = Bs4[tt][1];
                *(float4*)(Bv+ 8) = Bs4[tt][2];
                *(float4*)(Bv+12) = Bs4[tt][3];
                *(float4*)(Cv+ 0) = Cs4[tt][0];
                *(float4*)(Cv+ 4) = Cs4[tt][1];
                *(float4*)(Cv+ 8) = Cs4[tt][2];
                *(float4*)(Cv+12) = Cs4[tt][3];
                #pragma unroll
                for (int n = 0; n < 16; n++){
                    a *= e1;
                    h[n] = fmaf(a, h[n], du * Bv[n]);
                    y = fmaf(h[n], Cv[n], y);
                }
                ys[d][t] = y;
            }
        } else {
            for (int t = 0; t < 16; t++){
                int tt = ts*16 + t;
                float4 dv = dtr4[tt];
                float v = fmaf(wt3,dv.w, fmaf(wt2,dv.z, fmaf(wt1,dv.y, fmaf(wt0,dv.x, bt))));
                float dtv = softplus_fast(v);
                float uv = us[d][t];
                float du = dtv * uv;
                float y = uv * Dd;
                float Bv[16], Cv[16];
                *(float4*)(Bv+ 0) = Bs4[tt][0];
                *(float4*)(Bv+ 4) = Bs4[tt][1];
                *(float4*)(Bv+ 8) = Bs4[tt][2];
                *(float4*)(Bv+12) = Bs4[tt][3];
                *(float4*)(Cv+ 0) = Cs4[tt][0];
                *(float4*)(Cv+ 4) = Cs4[tt][1];
                *(float4*)(Cv+ 8) = Cs4[tt][2];
                *(float4*)(Cv+12) = Cs4[tt][3];
                #pragma unroll
                for (int n = 0; n < 16; n++){
                    float a = __expf(dtv * A[n]);
                    h[n] = fmaf(a, h[n], du * Bv[n]);
                    y = fmaf(h[n], Cv[n], y);
                }
                ys[d][t] = y;
            }
        }
        __syncthreads();
        for (int idx = tid; idx < 128*8; idx += 128){
            int r = idx >> 3, jp = (idx & 7) << 1;
            unsigned zp = *(const unsigned*)&g_z[((size_t)b*DIN + r)*LL + l0 + ts*16 + jp];
            float y0 = ys[r][jp]   * siluf(bflo_f(zp));
            float y1 = ys[r][jp+1] * siluf(bfhi_f(zp));
            *(unsigned*)&g_yz[((size_t)b*DIN + r)*LL + l0 + ts*16 + jp] = pack_bf2(y0, y1);
        }
    }
}

__global__ __launch_bounds__(256) void k_Wc(const float* __restrict__ aw,
                                            const float* __restrict__ ow){
    int i = blockIdx.x * 256 + threadIdx.x;
    if (i >= CC*DIN) return;
    int o = i >> 7, d = i & 127;
    float s = 0.f;
    for (int c = 0; c < 64; c++) s = fmaf(aw[o*64 + c], ow[c*128 + d], s);
    g_Wc[i] = s;
}

// ---------------- out_proj (+residual, +gn2 stats), double-buffered ----------------
__global__ __launch_bounds__(256) void k_outproj(const float* __restrict__ x){
    __shared__ unsigned Xs[2*32*XSTRIDE];
    __shared__ float rsw[8], rssw[8];
    int b = blockIdx.y;
    int l0 = blockIdx.x * 128;
    int tid = threadIdx.x;
    int wid = tid >> 5, lane = tid & 31;
    int gid = lane >> 2, tig = lane & 3;
    int m0 = (wid & 3) * 16, n0 = (wid >> 2) * 64;
    int cth = tid >> 6;
    int jpth = (tid & 63) << 1;
    float acc[8][4];
    #pragma unroll
    for (int i = 0; i < 8; i++){ acc[i][0]=acc[i][1]=acc[i][2]=acc[i][3]=0.f; }
    int row0 = m0 + gid, row1 = m0 + gid + 8;
    unsigned ld[8];
    #pragma unroll
    for (int s = 0; s < 8; s++){
        int c = cth + s*4;
        ld[s] = *(const unsigned*)&g_yz[((size_t)b*DIN + c)*LL + l0 + jpth];
    }
    int cur = 0;
    for (int kci = 0; kci < 4; kci++){
        int kc = kci*32;
        unsigned* Xb = Xs + cur*32*XSTRIDE;
        #pragma unroll
        for (int s = 0; s < 8; s++){
            int c = cth + s*4;
            Xb[c*XSTRIDE + jpth]     = bflo(ld[s]);
            Xb[c*XSTRIDE + jpth + 1] = bfhi(ld[s]);
        }
        __syncthreads();
        if (kci < 3){
            int kcn = kc + 32;
            #pragma unroll
            for (int s = 0; s < 8; s++){
                int c = cth + s*4;
                ld[s] = *(const unsigned*)&g_yz[((size_t)b*DIN + kcn + c)*LL + l0 + jpth];
            }
        }
        #pragma unroll
        for (int kk = 0; kk < 4; kk++){
            int k0 = kk*8;
            int kcol = kc + k0 + tig;
            unsigned a0 = f2tf(g_Wc[row0*128 + kcol]);
            unsigned a1 = f2tf(g_Wc[row1*128 + kcol]);
            unsigned a2 = f2tf(g_Wc[row0*128 + kcol + 4]);
            unsigned a3 = f2tf(g_Wc[row1*128 + kcol + 4]);
            mma8(acc, Xb, k0, n0, gid, tig, a0, a1, a2, a3);
        }
        cur ^= 1;
    }
    float s = 0.f, ss = 0.f;
    #pragma unroll
    for (int nt = 0; nt < 8; nt++){
        int colg = l0 + n0 + nt*8 + 2*tig;
        float2 xr0 = *(const float2*)&x[((size_t)b*CC + row0)*LL + colg];
        float2 xr1 = *(const float2*)&x[((size_t)b*CC + row1)*LL + colg];
        float v0 = acc[nt][0] + xr0.x, v1 = acc[nt][1] + xr0.y;
        float v2 = acc[nt][2] + xr1.x, v3 = acc[nt][3] + xr1.y;
        *(float2*)&g_x1[((size_t)b*CC + row0)*LL + colg] = make_float2(v0, v1);
        *(float2*)&g_x1[((size_t)b*CC + row1)*LL + colg] = make_float2(v2, v3);
        s += v0 + v1 + v2 + v3;
        ss += v0*v0 + v1*v1 + v2*v2 + v3*v3;
    }
    #pragma unroll
    for (int o = 16; o > 0; o >>= 1){
        s  += __shfl_down_sync(0xffffffffu, s,  o);
        ss += __shfl_down_sync(0xffffffffu, ss, o);
    }
    if (lane == 0){ rsw[wid] = s; rssw[wid] = ss; }
    __syncthreads();
    if (tid == 0){
        float a = 0.f, q = 0.f;
        for (int i = 0; i < 8; i++){ a += rsw[i]; q += rssw[i]; }
        g_part2[(b*128 + blockIdx.x)*2 + 0] = a;
        g_part2[(b*128 + blockIdx.x)*2 + 1] = q;
    }
}

// ---------------- GDFN pin (t stored bf16) ----------------
__global__ __launch_bounds__(256) void k_pin(const float* __restrict__ w){
    __shared__ unsigned Xs[64*XSTRIDE];
    int b = blockIdx.y;
    int l0 = blockIdx.x * 128;
    int tid = threadIdx.x;
    int wid = tid >> 5, lane = tid & 31;
    int gid = lane >> 2, tig = lane & 3;
    int m0 = (wid & 3) * 16, n0 = (wid >> 2) * 64;
    const float* scp = g_sc + (BB + b)*CC*2;
    for (int i = tid; i < 64*128; i += 256){
        int c = i >> 7, j = i & 127;
        Xs[c*XSTRIDE + j] = f2tf(fmaf(g_x1[((size_t)b*CC + c)*LL + l0 + j], scp[c*2], scp[c*2+1]));
    }
    __syncthreads();
    for (int og = 0; og < 6; og++){
        float acc[8][4];
        #pragma unroll
        for (int i = 0; i < 8; i++){ acc[i][0]=acc[i][1]=acc[i][2]=acc[i][3]=0.f; }
        int row0 = og*64 + m0 + gid, row1 = row0 + 8;
        #pragma unroll
        for (int kk = 0; kk < 8; kk++){
            int k0 = kk*8;
            int kcol = k0 + tig;
            unsigned a0 = (row0 < HID2) ? f2tf(w[row0*64 + kcol])     : 0u;
            unsigned a1 = (row1 < HID2) ? f2tf(w[row1*64 + kcol])     : 0u;
            unsigned a2 = (row0 < HID2) ? f2tf(w[row0*64 + kcol + 4]) : 0u;
            unsigned a3 = (row1 < HID2) ? f2tf(w[row1*64 + kcol + 4]) : 0u;
            mma8(acc, Xs, k0, n0, gid, tig, a0, a1, a2, a3);
        }
        #pragma unroll
        for (int nt = 0; nt < 8; nt++){
            int colg = l0 + n0 + nt*8 + 2*tig;
            if (row0 < HID2)
                *(unsigned*)&g_t[((size_t)b*HID2 + row0)*LL + colg] = pack_bf2(acc[nt][0], acc[nt][1]);
            if (row1 < HID2)
                *(unsigned*)&g_t[((size_t)b*HID2 + row1)*LL + colg] = pack_bf2(acc[nt][2], acc[nt][3]);
        }
    }
}

__global__ void k_dw(const float* __restrict__ dww){
    __shared__ float s1[10][34], s2[10][34];
    int bc = blockIdx.z;
    int b = bc / HIDc, ch = bc % HIDc;
    int w0 = blockIdx.x * 32, h0 = blockIdx.y * 8;
    int tid = threadIdx.y * 32 + threadIdx.x;
    const __nv_bfloat16* t1 = g_t + ((size_t)b*HID2 + ch)*LL;
    const __nv_bfloat16* t2 = g_t + ((size_t)b*HID2 + ch + HIDc)*LL;
    for (int idx = tid; idx < 10*34; idx += 256){
        int hh = idx / 34 - 1 + h0, ww = idx % 34 - 1 + w0;
        bool ok = (hh >= 0 && hh < HH && ww >= 0 && ww < WW);
        s1[idx/34][idx%34] = ok ? __bfloat162float(t1[hh*WW + ww]) : 0.f;
        s2[idx/34][idx%34] = ok ? __bfloat162float(t2[hh*WW + ww]) : 0.f;
    }
    __syncthreads();
    int th = threadIdx.y, tw = threadIdx.x;
    const float* w1 = dww + ch*9;
    const float* w2 = dww + (ch + HIDc)*9;
    float a1 = 0.f, a2 = 0.f;
    #pragma unroll
    for (int dy = 0; dy < 3; dy++)
        #pragma unroll
        for (int dx = 0; dx < 3; dx++){
            a1 = fmaf(w1[dy*3+dx], s1[th+dy][tw+dx], a1);
            a2 = fmaf(w2[dy*3+dx], s2[th+dy][tw+dx], a2);
        }
    g_gg[((size_t)b*HIDc + ch)*LL + (h0+th)*WW + w0+tw] =
        __float2bfloat16_rn(gelu_tanh(a1) * a2);
}

// ---------------- pout (+residual), K=192 padded, double-buffered ----------------
__global__ __launch_bounds__(256) void k_pout(const float* __restrict__ w,
                                              float* __restrict__ out){
    __shared__ unsigned Xs[2*32*XSTRIDE];
    int b = blockIdx.y;
    int l0 = blockIdx.x * 128;
    int tid = threadIdx.x;
    int wid = tid >> 5, lane = tid & 31;
    int gid = lane >> 2, tig = lane & 3;
    int m0 = (wid & 3) * 16, n0 = (wid >> 2) * 64;
    int cth = tid >> 6;
    int jpth = (tid & 63) << 1;
    float acc[8][4];
    #pragma unroll
    for (int i = 0; i < 8; i++){ acc[i][0]=acc[i][1]=acc[i][2]=acc[i][3]=0.f; }
    int row0 = m0 + gid, row1 = m0 + gid + 8;
    unsigned ld[8];
    #pragma unroll
    for (int s = 0; s < 8; s++){
        int cg = cth + s*4;
        ld[s] = (cg < HIDc) ? *(const unsigned*)&g_gg[((size_t)b*HIDc + cg)*LL + l0 + jpth] : 0u;
    }
    int cur = 0;
    for (int kci = 0; kci < 6; kci++){
        int kc = kci*32;
        unsigned* Xb = Xs + cur*32*XSTRIDE;
        #pragma unroll
        for (int s = 0; s < 8; s++){
            int c = cth + s*4;
            Xb[c*XSTRIDE + jpth]     = bflo(ld[s]);
            Xb[c*XSTRIDE + jpth + 1] = bfhi(ld[s]);
        }
        __syncthreads();
        if (kci < 5){
            int kcn = kc + 32;
            #pragma unroll
            for (int s = 0; s < 8; s++){
                int cg = kcn + cth + s*4;
                ld[s] = (cg < HIDc) ? *(const unsigned*)&g_gg[((size_t)b*HIDc + cg)*LL + l0 + jpth] : 0u;
            }
        }
        #pragma unroll
        for (int kk = 0; kk < 4; kk++){
            int k0 = kk*8;
            int kcol = kc + k0 + tig;
            unsigned a0 = (kcol < HIDc)     ? f2tf(w[row0*HIDc + kcol])     : 0u;
            unsigned a1 = (kcol < HIDc)     ? f2tf(w[row1*HIDc + kcol])     : 0u;
            unsigned a2 = (kcol + 4 < HIDc) ? f2tf(w[row0*HIDc + kcol + 4]) : 0u;
            unsigned a3 = (kcol + 4 < HIDc) ? f2tf(w[row1*HIDc + kcol + 4]) : 0u;
            mma8(acc, Xb, k0, n0, gid, tig, a0, a1, a2, a3);
        }
        cur ^= 1;
    }
    #pragma unroll
    for (int nt = 0; nt < 8; nt++){
        int colg = l0 + n0 + nt*8 + 2*tig;
        float2 xr0 = *(const float2*)&g_x1[((size_t)b*CC + row0)*LL + colg];
        float2 xr1 = *(const float2*)&g_x1[((size_t)b*CC + row1)*LL + colg];
        *(float2*)&out[((size_t)b*CC + row0)*LL + colg] =
            make_float2(acc[nt][0] + xr0.x, acc[nt][1] + xr0.y);
        *(float2*)&out[((size_t)b*CC + row1)*LL + colg] =
            make_float2(acc[nt][2] + xr1.x, acc[nt][3] + xr1.y);
    }
}

extern "C" void kernel_launch(void* const* d_in, const int* in_sizes, int n_in,
                              void* d_out, int out_size){
    const float* x        = (const float*)d_in[0];
    const float* gn_a_g   = (const float*)d_in[1];
    const float* gn_a_b   = (const float*)d_in[2];
    const float* in_proj  = (const float*)d_in[3];
    const float* conv1d_w = (const float*)d_in[4];
    const float* conv1d_b = (const float*)d_in[5];
    const float* x_proj   = (const float*)d_in[6];
    const float* dt_w     = (const float*)d_in[7];
    const float* dt_b     = (const float*)d_in[8];
    const float* A_log    = (const float*)d_in[9];
    const float* D_param  = (const float*)d_in[10];
    const float* out_proj = (const float*)d_in[11];
    const float* attn_out = (const float*)d_in[12];
    const float* gn2_g    = (const float*)d_in[13];
    const float* gn2_b    = (const float*)d_in[14];
    const float* pin_w    = (const float*)d_in[15];
    const float* dw_w     = (const float*)d_in[16];
    const float* pout_w   = (const float*)d_in[17];
    float* out = (float*)d_out;

    const int SMEM_IPC = 64*XSTRIDE*4 + 128*132*4 + 64*4*4;
    cudaFuncSetAttribute(k_inprojconv, cudaFuncAttributeMaxDynamicSharedMemorySize, SMEM_IPC);

    k_stats1<<<dim3(256, BB), 256>>>(x);
    k_fin<<<BB, 256>>>(0, gn_a_g, gn_a_b);
    k_inprojconv<<<dim3(128, BB), 256, SMEM_IPC>>>(x, in_proj, conv1d_w, conv1d_b);
    k_xdbl<<<dim3(128, BB), 256>>>(x_proj);
    k_passA<<<dim3(NCHK, BB), 128>>>(A_log, dt_w, dt_b);
    k_passB<<<64, 64>>>();
    k_passC<<<dim3(NCHK, BB), 128>>>(A_log, dt_w, dt_b, D_param);
    k_Wc<<<32, 256>>>(attn_out, out_proj);
    k_outproj<<<dim3(128, BB), 256>>>(x);
    k_fin<<<BB, 256>>>(1, gn2_g, gn2_b);
    k_pin<<<dim3(128, BB), 256>>>(pin_w);
    k_dw<<<dim3(4, 16, BB*HIDc), dim3(32, 8)>>>(dw_w);
    k_pout<<<dim3(128, BB), 256>>>(pout_w, out);
}

// round 14
// speedup vs baseline: 1.1187x; 1.0083x over previous
#include <cuda_runtime.h>
#include <cuda_bf16.h>
#include <cstdint>

#define BB   2
#define CC   64
#define LL   16384
#define DIN  128
#define NST  16
#define HIDc 170
#define HID2 340
#define NCHK 256
#define CHK  64
#define HH   128
#define WW   128
#define XSTRIDE 136
#define UCS  66

// ---------------- scratch ----------------
__device__ __nv_bfloat16 g_z [BB*DIN*LL];
__device__ __nv_bfloat16 g_uc[BB*DIN*LL];
__device__ __nv_bfloat16 g_yz[BB*DIN*LL];
__device__ __nv_bfloat16 g_t [BB*HID2*LL];
__device__ __nv_bfloat16 g_gg[BB*HIDc*LL];
__device__ float g_xdbl[BB*40*LL];
__device__ float g_x1  [BB*CC*LL];
__device__ float g_chA [BB*DIN*NCHK*NST];
__device__ float g_chB [BB*DIN*NCHK*NST];
__device__ float g_h0  [BB*DIN*NCHK*NST];
__device__ float g_part1[BB*256*2];
__device__ float g_part2[BB*128*2];
__device__ float g_sc  [2*BB*CC*2];
__device__ float g_Wc  [CC*DIN];

// ---------------- helpers ----------------
__device__ __forceinline__ float siluf(float x){ return x / (1.0f + __expf(-x)); }
__device__ __forceinline__ float softplus_fast(float x){
    return (x > 20.f) ? x : __logf(1.0f + __expf(x));
}
__device__ __forceinline__ float gelu_tanh(float x){
    float x3 = x * x * x;
    float u  = 0.7978845608028654f * fmaf(0.044715f, x3, x);
    float th = 1.0f - 2.0f / (__expf(2.0f * u) + 1.0f);
    return 0.5f * x * (1.0f + th);
}
__device__ __forceinline__ unsigned f2tf(float f){
    unsigned r;
    asm("cvt.rna.tf32.f32 %0, %1;" : "=r"(r) : "f"(f));
    return r;
}
__device__ __forceinline__ unsigned bflo(unsigned p){ return p << 16; }
__device__ __forceinline__ unsigned bfhi(unsigned p){ return p & 0xFFFF0000u; }
__device__ __forceinline__ float bflo_f(unsigned p){ return __uint_as_float(p << 16); }
__device__ __forceinline__ float bfhi_f(unsigned p){ return __uint_as_float(p & 0xFFFF0000u); }
__device__ __forceinline__ unsigned pack_bf2(float a, float b){
    __nv_bfloat162 v = __float22bfloat162_rn(make_float2(a, b));
    return *(unsigned*)&v;
}
__device__ __forceinline__ void mma8(float (&acc)[8][4], const unsigned* __restrict__ Xs,
                                     int k0, int n0, int gid, int tig,
                                     unsigned a0, unsigned a1, unsigned a2, unsigned a3){
    #pragma unroll
    for (int nt = 0; nt < 8; nt++){
        int col = n0 + nt*8 + gid;
        unsigned b0 = Xs[(k0+tig)*XSTRIDE + col];
        unsigned b1 = Xs[(k0+tig+4)*XSTRIDE + col];
        asm volatile("mma.sync.aligned.m16n8k8.row.col.f32.tf32.tf32.f32 "
            "{%0,%1,%2,%3}, {%4,%5,%6,%7}, {%8,%9}, {%0,%1,%2,%3};"
            : "+f"(acc[nt][0]), "+f"(acc[nt][1]), "+f"(acc[nt][2]), "+f"(acc[nt][3])
            : "r"(a0), "r"(a1), "r"(a2), "r"(a3), "r"(b0), "r"(b1));
    }
}

// ---------------- GN stats ----------------
__global__ __launch_bounds__(256) void k_stats1(const float* __restrict__ x){
    int b = blockIdx.y;
    const float* xb = x + (size_t)b*CC*LL;
    int base = blockIdx.x * 4096;
    float s = 0.f, ss = 0.f;
    for (int i = threadIdx.x; i < 4096; i += 256){
        float v = xb[base + i]; s += v; ss = fmaf(v, v, ss);
    }
    #pragma unroll
    for (int o = 16; o > 0; o >>= 1){
        s  += __shfl_down_sync(0xffffffffu, s,  o);
        ss += __shfl_down_sync(0xffffffffu, ss, o);
    }
    __shared__ float rs[8], rss[8];
    int w = threadIdx.x >> 5, ln = threadIdx.x & 31;
    if (ln == 0){ rs[w] = s; rss[w] = ss; }
    __syncthreads();
    if (threadIdx.x == 0){
        float a = 0.f, q = 0.f;
        for (int i = 0; i < 8; i++){ a += rs[i]; q += rss[i]; }
        g_part1[(b*256 + blockIdx.x)*2 + 0] = a;
        g_part1[(b*256 + blockIdx.x)*2 + 1] = q;
    }
}

__global__ __launch_bounds__(256) void k_fin(int which, const float* __restrict__ gam,
                                             const float* __restrict__ bet){
    const float* part = (which == 0) ? g_part1 : g_part2;
    int np = (which == 0) ? 256 : 128;
    int b = blockIdx.x;
    __shared__ float sh[512];
    float a = 0.f, q = 0.f;
    for (int i = threadIdx.x; i < np; i += 256){
        a += part[(b*np + i)*2 + 0];
        q += part[(b*np + i)*2 + 1];
    }
    sh[threadIdx.x] = a; sh[256 + threadIdx.x] = q;
    __syncthreads();
    for (int s = 128; s > 0; s >>= 1){
        if (threadIdx.x < s){
            sh[threadIdx.x]       += sh[threadIdx.x + s];
            sh[256 + threadIdx.x] += sh[256 + threadIdx.x + s];
        }
        __syncthreads();
    }
    if (threadIdx.x < CC){
        int c = threadIdx.x;
        float n  = (float)CC * (float)LL;
        float mu = sh[0] / n;
        float var = sh[256] / n - mu*mu;
        float rsd = rsqrtf(var + 1e-5f);
        g_sc[((which*BB + b)*CC + c)*2 + 0] = rsd * gam[c];
        g_sc[((which*BB + b)*CC + c)*2 + 1] = bet[c] - mu * rsd * gam[c];
    }
}

// ---------------- in_proj + conv1d + silu + x_proj fused ----------------
__global__ __launch_bounds__(256) void k_inprojconv(const float* __restrict__ x,
                                                    const float* __restrict__ w,
                                                    const float* __restrict__ cw,
                                                    const float* __restrict__ cb,
                                                    const float* __restrict__ xpw){
    extern __shared__ char smem_raw[];
    unsigned* Xs = (unsigned*)smem_raw;                 // 64*XSTRIDE words; later reused as Ucs [128][UCS]
    float* Us = (float*)(Xs + 64*XSTRIDE);              // [128][132]
    float* xh = Us + 128*132;                           // [64][4]
    int b = blockIdx.y;
    int l0 = blockIdx.x * 128;
    int tid = threadIdx.x;
    int wid = tid >> 5, lane = tid & 31;
    int gid = lane >> 2, tig = lane & 3;
    int m0 = (wid & 3) * 16, n0 = (wid >> 2) * 64;
    const float* scp = g_sc + b*CC*2;
    for (int i = tid; i < 64*128; i += 256){
        int c = i >> 7, j = i & 127;
        Xs[c*XSTRIDE + j] = f2tf(fmaf(x[((size_t)b*CC + c)*LL + l0 + j], scp[c*2], scp[c*2+1]));
    }
    if (tid < 64*3){
        int c = tid / 3, j = tid % 3;
        float v = 0.f;
        if (l0 > 0) v = fmaf(x[((size_t)b*CC + c)*LL + l0 - 3 + j], scp[c*2], scp[c*2+1]);
        xh[c*4 + j] = v;
    }
    __syncthreads();
    if (tid < 128){
        int d = tid;
        const float* wr = w + d*64;
        float h0v = 0.f, h1v = 0.f, h2v = 0.f;
        #pragma unroll 8
        for (int c = 0; c < 64; c++){
            float wv = wr[c];
            h0v = fmaf(wv, xh[c*4 + 0], h0v);
            h1v = fmaf(wv, xh[c*4 + 1], h1v);
            h2v = fmaf(wv, xh[c*4 + 2], h2v);
        }
        Us[d*132 + 0] = h0v; Us[d*132 + 1] = h1v; Us[d*132 + 2] = h2v;
    }
    for (int og = 0; og < 4; og++){
        float acc[8][4];
        #pragma unroll
        for (int i = 0; i < 8; i++){ acc[i][0]=acc[i][1]=acc[i][2]=acc[i][3]=0.f; }
        #pragma unroll
        for (int kk = 0; kk < 8; kk++){
            int k0 = kk*8;
            const float* wr = w + (og*64 + m0 + gid)*64 + k0 + tig;
            unsigned a0 = f2tf(wr[0]);
            unsigned a1 = f2tf(wr[8*64]);
            unsigned a2 = f2tf(wr[4]);
            unsigned a3 = f2tf(wr[8*64 + 4]);
            mma8(acc, Xs, k0, n0, gid, tig, a0, a1, a2, a3);
        }
        int dbase = (og & 1) * 64;
        int r0 = dbase + m0 + gid;
        if (og >= 2){
            #pragma unroll
            for (int nt = 0; nt < 8; nt++){
                int colg = l0 + n0 + nt*8 + 2*tig;
                *(unsigned*)&g_z[((size_t)b*DIN + r0)*LL + colg]     = pack_bf2(acc[nt][0], acc[nt][1]);
                *(unsigned*)&g_z[((size_t)b*DIN + r0 + 8)*LL + colg] = pack_bf2(acc[nt][2], acc[nt][3]);
            }
        } else {
            #pragma unroll
            for (int nt = 0; nt < 8; nt++){
                int cl = n0 + nt*8 + 2*tig;
                Us[r0*132 + cl + 3]       = acc[nt][0];
                Us[r0*132 + cl + 4]       = acc[nt][1];
                Us[(r0+8)*132 + cl + 3]   = acc[nt][2];
                Us[(r0+8)*132 + cl + 4]   = acc[nt][3];
            }
        }
    }
    __syncthreads();     // Xs (in_proj X tile) dead from here; reuse as Ucs
    unsigned* Ucs = Xs;  // [128][UCS] bf16 pairs of uc
    {
        int lq = tid & 31, dgrp = tid >> 5;
        for (int k = 0; k < 16; k++){
            int d = dgrp*16 + k;
            float4 q0 = *(float4*)&Us[d*132 + 4*lq];
            float4 q1 = *(float4*)&Us[d*132 + 4*lq + 4];
            float w0 = cw[d*4+0], w1 = cw[d*4+1], w2 = cw[d*4+2], w3 = cw[d*4+3];
            float bv = cb[d];
            float y0 = fmaf(w3,q0.w, fmaf(w2,q0.z, fmaf(w1,q0.y, fmaf(w0,q0.x, bv))));
            float y1 = fmaf(w3,q1.x, fmaf(w2,q0.w, fmaf(w1,q0.z, fmaf(w0,q0.y, bv))));
            float y2 = fmaf(w3,q1.y, fmaf(w2,q1.x, fmaf(w1,q0.w, fmaf(w0,q0.z, bv))));
            float y3 = fmaf(w3,q1.z, fmaf(w2,q1.y, fmaf(w1,q1.x, fmaf(w0,q0.w, bv))));
            uint2 o;
            o.x = pack_bf2(siluf(y0), siluf(y1));
            o.y = pack_bf2(siluf(y2), siluf(y3));
            *(uint2*)&g_uc[((size_t)b*DIN + d)*LL + l0 + 4*lq] = o;
            Ucs[d*UCS + 2*lq]     = o.x;
            Ucs[d*UCS + 2*lq + 1] = o.y;
        }
    }
    __syncthreads();
    // x_proj GEMM from smem uc tile: rows 0..35, K = 128 (d), cols = 128 (l)
    {
        float acc[8][4];
        #pragma unroll
        for (int i = 0; i < 8; i++){ acc[i][0]=acc[i][1]=acc[i][2]=acc[i][3]=0.f; }
        int row0 = m0 + gid, row1 = m0 + gid + 8;
        int sel = gid & 1;
        #pragma unroll
        for (int kk = 0; kk < 16; kk++){
            int k0 = kk*8;
            int kcol = k0 + tig;
            unsigned a0 = (row0 < 36) ? f2tf(xpw[row0*128 + kcol])     : 0u;
            unsigned a1 = (row1 < 36) ? f2tf(xpw[row1*128 + kcol])     : 0u;
            unsigned a2 = (row0 < 36) ? f2tf(xpw[row0*128 + kcol + 4]) : 0u;
            unsigned a3 = (row1 < 36) ? f2tf(xpw[row1*128 + kcol + 4]) : 0u;
            #pragma unroll
            for (int nt = 0; nt < 8; nt++){
                int col = n0 + nt*8 + gid;
                int pidx = col >> 1;
                unsigned p0 = Ucs[(k0+tig)*UCS + pidx];
                unsigned p1 = Ucs[(k0+tig+4)*UCS + pidx];
                unsigned b0 = sel ? bfhi(p0) : bflo(p0);
                unsigned b1 = sel ? bfhi(p1) : bflo(p1);
                asm volatile("mma.sync.aligned.m16n8k8.row.col.f32.tf32.tf32.f32 "
                    "{%0,%1,%2,%3}, {%4,%5,%6,%7}, {%8,%9}, {%0,%1,%2,%3};"
                    : "+f"(acc[nt][0]), "+f"(acc[nt][1]), "+f"(acc[nt][2]), "+f"(acc[nt][3])
                    : "r"(a0), "r"(a1), "r"(a2), "r"(a3), "r"(b0), "r"(b1));
            }
        }
        #pragma unroll
        for (int nt = 0; nt < 8; nt++){
            int colg = l0 + n0 + nt*8 + 2*tig;
            if (row0 < 36)
                *(float2*)&g_xdbl[((size_t)b*40 + row0)*LL + colg] = make_float2(acc[nt][0], acc[nt][1]);
            if (row1 < 36)
                *(float2*)&g_xdbl[((size_t)b*40 + row1)*LL + colg] = make_float2(acc[nt][2], acc[nt][3]);
        }
    }
}

// ---------------- scan passA ----------------
__global__ __launch_bounds__(128) void k_passA(const float* __restrict__ A_log,
                                               const float* __restrict__ dtw,
                                               const float* __restrict__ dtb){
    __shared__ float4 Bs4[CHK][4];
    __shared__ float4 dtr4[CHK];
    __shared__ float us [DIN][33];
    int b = blockIdx.y, chn = blockIdx.x;
    int l0 = chn * CHK;
    int tid = threadIdx.x;
    float* Bsf = (float*)Bs4;
    float* dtrf = (float*)dtr4;
    for (int idx = tid; idx < 16*CHK; idx += 128){
        int r = idx >> 6, j = idx & 63;
        Bsf[j*16 + r] = g_xdbl[((size_t)b*40 + 4 + r)*LL + l0 + j];
    }
    for (int idx = tid; idx < 4*CHK; idx += 128){
        int r = idx >> 6, j = idx & 63;
        dtrf[j*4 + r] = g_xdbl[((size_t)b*40 + r)*LL + l0 + j];
    }
    int d = tid;
    float wt0 = dtw[d*4+0], wt1 = dtw[d*4+1], wt2 = dtw[d*4+2], wt3 = dtw[d*4+3];
    float bt = dtb[d];
    float A[16], ap[16], h[16];
    float P = 1.f;
    bool pw = true;
    #pragma unroll
    for (int n = 0; n < 16; n++){
        A[n] = -__expf(A_log[d*16 + n]);
        pw = pw && (fabsf(A[n] + (float)(n+1)) < 1e-5f);
        ap[n] = 1.f; h[n] = 0.f;
    }
    unsigned uld[16];
    #pragma unroll
    for (int s = 0; s < 16; s++){
        int idx = tid + s*128;
        int r = idx >> 4, jp = (idx & 15) << 1;
        uld[s] = *(const unsigned*)&g_uc[((size_t)b*DIN + r)*LL + l0 + jp];
    }
    for (int ts = 0; ts < CHK/32; ts++){
        __syncthreads();
        #pragma unroll
        for (int s = 0; s < 16; s++){
            int idx = tid + s*128;
            int r = idx >> 4, jp = (idx & 15) << 1;
            us[r][jp]   = bflo_f(uld[s]);
            us[r][jp+1] = bfhi_f(uld[s]);
        }
        __syncthreads();
        if (ts < CHK/32 - 1){
            #pragma unroll
            for (int s = 0; s < 16; s++){
                int idx = tid + s*128;
                int r = idx >> 4, jp = (idx & 15) << 1;
                uld[s] = *(const unsigned*)&g_uc[((size_t)b*DIN + r)*LL + l0 + (ts+1)*32 + jp];
            }
        }
        if (pw){
            for (int t = 0; t < 32; t++){
                int tt = ts*32 + t;
                float4 dv = dtr4[tt];
                float v = fmaf(wt3,dv.w, fmaf(wt2,dv.z, fmaf(wt1,dv.y, fmaf(wt0,dv.x, bt))));
                float dtv = softplus_fast(v);
                float du  = dtv * us[d][t];
                float e1  = __expf(-dtv);
                P *= e1;
                float Bv[16];
                *(float4*)(Bv+ 0) = Bs4[tt][0];
                *(float4*)(Bv+ 4) = Bs4[tt][1];
                *(float4*)(Bv+ 8) = Bs4[tt][2];
                *(float4*)(Bv+12) = Bs4[tt][3];
                float a = 1.f;
                #pragma unroll
                for (int n = 0; n < 16; n++){
                    a *= e1;
                    h[n] = fmaf(a, h[n], du * Bv[n]);
                }
            }
        } else {
            for (int t = 0; t < 32; t++){
                int tt = ts*32 + t;
                float4 dv = dtr4[tt];
                float v = fmaf(wt3,dv.w, fmaf(wt2,dv.z, fmaf(wt1,dv.y, fmaf(wt0,dv.x, bt))));
                float dtv = softplus_fast(v);
                float du  = dtv * us[d][t];
                float Bv[16];
                *(float4*)(Bv+ 0) = Bs4[tt][0];
                *(float4*)(Bv+ 4) = Bs4[tt][1];
                *(float4*)(Bv+ 8) = Bs4[tt][2];
                *(float4*)(Bv+12) = Bs4[tt][3];
                #pragma unroll
                for (int n = 0; n < 16; n++){
                    float a = __expf(dtv * A[n]);
                    h[n] = fmaf(a, h[n], du * Bv[n]);
                    ap[n] *= a;
                }
            }
        }
    }
    size_t base = (((size_t)b*DIN + d)*NCHK + chn)*16;
    if (pw){
        float a = 1.f;
        #pragma unroll
        for (int n = 0; n < 16; n++){ a *= P; g_chA[base+n] = a; g_chB[base+n] = h[n]; }
    } else {
        #pragma unroll
        for (int n = 0; n < 16; n++){ g_chA[base+n] = ap[n]; g_chB[base+n] = h[n]; }
    }
}

__global__ __launch_bounds__(64) void k_passB(){
    int i = blockIdx.x * 64 + threadIdx.x;
    int n = i & 15, bd = i >> 4;
    float h = 0.f;
    size_t base = (size_t)bd*NCHK*16 + n;
    for (int ch = 0; ch < NCHK; ch++){
        size_t idx = base + (size_t)ch*16;
        g_h0[idx] = h;
        h = fmaf(g_chA[idx], h, g_chB[idx]);
    }
}

// ---------------- scan passC ----------------
__global__ __launch_bounds__(128) void k_passC(const float* __restrict__ A_log,
                                               const float* __restrict__ dtw,
                                               const float* __restrict__ dtb,
                                               const float* __restrict__ Dp){
    __shared__ float4 Bs4[CHK][4];
    __shared__ float4 Cs4[CHK][4];
    __shared__ float4 dtr4[CHK];
    __shared__ float us [DIN][17];
    __shared__ float ys [DIN][17];
    int b = blockIdx.y, chn = blockIdx.x;
    int l0 = chn * CHK;
    int tid = threadIdx.x;
    float* Bsf = (float*)Bs4;
    float* Csf = (float*)Cs4;
    float* dtrf = (float*)dtr4;
    for (int idx = tid; idx < 16*CHK; idx += 128){
        int r = idx >> 6, j = idx & 63;
        Bsf[j*16 + r] = g_xdbl[((size_t)b*40 +  4 + r)*LL + l0 + j];
        Csf[j*16 + r] = g_xdbl[((size_t)b*40 + 20 + r)*LL + l0 + j];
    }
    for (int idx = tid; idx < 4*CHK; idx += 128){
        int r = idx >> 6, j = idx & 63;
        dtrf[j*4 + r] = g_xdbl[((size_t)b*40 + r)*LL + l0 + j];
    }
    int d = tid;
    float wt0 = dtw[d*4+0], wt1 = dtw[d*4+1], wt2 = dtw[d*4+2], wt3 = dtw[d*4+3];
    float bt = dtb[d];
    float A[16], h[16];
    bool pw = true;
    size_t hbase = (((size_t)b*DIN + d)*NCHK + chn)*16;
    #pragma unroll
    for (int n = 0; n < 16; n++){
        A[n] = -__expf(A_log[d*16 + n]);
        pw = pw && (fabsf(A[n] + (float)(n+1)) < 1e-5f);
        h[n] = g_h0[hbase + n];
    }
    float Dd = Dp[d];
    unsigned uld[8];
    #pragma unroll
    for (int s = 0; s < 8; s++){
        int idx = tid + s*128;
        int r = idx >> 3, jp = (idx & 7) << 1;
        uld[s] = *(const unsigned*)&g_uc[((size_t)b*DIN + r)*LL + l0 + jp];
    }
    for (int ts = 0; ts < CHK/16; ts++){
        __syncthreads();
        #pragma unroll
        for (int s = 0; s < 8; s++){
            int idx = tid + s*128;
            int r = idx >> 3, jp = (idx & 7) << 1;
            us[r][jp]   = bflo_f(uld[s]);
            us[r][jp+1] = bfhi_f(uld[s]);
        }
        __syncthreads();
        if (ts < CHK/16 - 1){
            #pragma unroll
            for (int s = 0; s < 8; s++){
                int idx = tid + s*128;
                int r = idx >> 3, jp = (idx & 7) << 1;
                uld[s] = *(const unsigned*)&g_uc[((size_t)b*DIN + r)*LL + l0 + (ts+1)*16 + jp];
            }
        }
        if (pw){
            for (int t = 0; t < 16; t++){
                int tt = ts*16 + t;
                float4 dv = dtr4[tt];
                float v = fmaf(wt3,dv.w, fmaf(wt2,dv.z, fmaf(wt1,dv.y, fmaf(wt0,dv.x, bt))));
                float dtv = softplus_fast(v);
                float uv = us[d][t];
                float du = dtv * uv;
                float e1 = __expf(-dtv);
                float a  = 1.f;
                float y = uv * Dd;
                float Bv[16], Cv[16];
                *(float4*)(Bv+ 0) = Bs4[tt][0];
                *(float4*)(Bv+ 4) = Bs4[tt][1];
                *(float4*)(Bv+ 8) = Bs4[tt][2];
                *(float4*)(Bv+12) = Bs4[tt][3];
                *(float4*)(Cv+ 0) = Cs4[tt][0];
                *(float4*)(Cv+ 4) = Cs4[tt][1];
                *(float4*)(Cv+ 8) = Cs4[tt][2];
                *(float4*)(Cv+12) = Cs4[tt][3];
                #pragma unroll
                for (int n = 0; n < 16; n++){
                    a *= e1;
                    h[n] = fmaf(a, h[n], du * Bv[n]);
                    y = fmaf(h[n], Cv[n], y);
                }
                ys[d][t] = y;
            }
        } else {
            for (int t = 0; t < 16; t++){
                int tt = ts*16 + t;
                float4 dv = dtr4[tt];
                float v = fmaf(wt3,dv.w, fmaf(wt2,dv.z, fmaf(wt1,dv.y, fmaf(wt0,dv.x, bt))));
                float dtv = softplus_fast(v);
                float uv = us[d][t];
                float du = dtv * uv;
                float y = uv * Dd;
                float Bv[16], Cv[16];
                *(float4*)(Bv+ 0) = Bs4[tt][0];
                *(float4*)(Bv+ 4) = Bs4[tt][1];
                *(float4*)(Bv+ 8) = Bs4[tt][2];
                *(float4*)(Bv+12) = Bs4[tt][3];
                *(float4*)(Cv+ 0) = Cs4[tt][0];
                *(float4*)(Cv+ 4) = Cs4[tt][1];
                *(float4*)(Cv+ 8) = Cs4[tt][2];
                *(float4*)(Cv+12) = Cs4[tt][3];
                #pragma unroll
                for (int n = 0; n < 16; n++){
                    float a = __expf(dtv * A[n]);
                    h[n] = fmaf(a, h[n], du * Bv[n]);
                    y = fmaf(h[n], Cv[n], y);
                }
                ys[d][t] = y;
            }
        }
        __syncthreads();
        for (int idx = tid; idx < 128*8; idx += 128){
            int r = idx >> 3, jp = (idx & 7) << 1;
            unsigned zp = *(const unsigned*)&g_z[((size_t)b*DIN + r)*LL + l0 + ts*16 + jp];
            float y0 = ys[r][jp]   * siluf(bflo_f(zp));
            float y1 = ys[r][jp+1] * siluf(bfhi_f(zp));
            *(unsigned*)&g_yz[((size_t)b*DIN + r)*LL + l0 + ts*16 + jp] = pack_bf2(y0, y1);
        }
    }
}

__global__ __launch_bounds__(256) void k_Wc(const float* __restrict__ aw,
                                            const float* __restrict__ ow){
    int i = blockIdx.x * 256 + threadIdx.x;
    if (i >= CC*DIN) return;
    int o = i >> 7, d = i & 127;
    float s = 0.f;
    for (int c = 0; c < 64; c++) s = fmaf(aw[o*64 + c], ow[c*128 + d], s);
    g_Wc[i] = s;
}

// ---------------- out_proj (+residual, +gn2 stats), double-buffered ----------------
__global__ __launch_bounds__(256) void k_outproj(const float* __restrict__ x){
    __shared__ unsigned Xs[2*32*XSTRIDE];
    __shared__ float rsw[8], rssw[8];
    int b = blockIdx.y;
    int l0 = blockIdx.x * 128;
    int tid = threadIdx.x;
    int wid = tid >> 5, lane = tid & 31;
    int gid = lane >> 2, tig = lane & 3;
    int m0 = (wid & 3) * 16, n0 = (wid >> 2) * 64;
    int cth = tid >> 6;
    int jpth = (tid & 63) << 1;
    float acc[8][4];
    #pragma unroll
    for (int i = 0; i < 8; i++){ acc[i][0]=acc[i][1]=acc[i][2]=acc[i][3]=0.f; }
    int row0 = m0 + gid, row1 = m0 + gid + 8;
    unsigned ld[8];
    #pragma unroll
    for (int s = 0; s < 8; s++){
        int c = cth + s*4;
        ld[s] = *(const unsigned*)&g_yz[((size_t)b*DIN + c)*LL + l0 + jpth];
    }
    int cur = 0;
    for (int kci = 0; kci < 4; kci++){
        int kc = kci*32;
        unsigned* Xb = Xs + cur*32*XSTRIDE;
        #pragma unroll
        for (int s = 0; s < 8; s++){
            int c = cth + s*4;
            Xb[c*XSTRIDE + jpth]     = bflo(ld[s]);
            Xb[c*XSTRIDE + jpth + 1] = bfhi(ld[s]);
        }
        __syncthreads();
        if (kci < 3){
            int kcn = kc + 32;
            #pragma unroll
            for (int s = 0; s < 8; s++){
                int c = cth + s*4;
                ld[s] = *(const unsigned*)&g_yz[((size_t)b*DIN + kcn + c)*LL + l0 + jpth];
            }
        }
        #pragma unroll
        for (int kk = 0; kk < 4; kk++){
            int k0 = kk*8;
            int kcol = kc + k0 + tig;
            unsigned a0 = f2tf(g_Wc[row0*128 + kcol]);
            unsigned a1 = f2tf(g_Wc[row1*128 + kcol]);
            unsigned a2 = f2tf(g_Wc[row0*128 + kcol + 4]);
            unsigned a3 = f2tf(g_Wc[row1*128 + kcol + 4]);
            mma8(acc, Xb, k0, n0, gid, tig, a0, a1, a2, a3);
        }
        cur ^= 1;
    }
    float s = 0.f, ss = 0.f;
    #pragma unroll
    for (int nt = 0; nt < 8; nt++){
        int colg = l0 + n0 + nt*8 + 2*tig;
        float2 xr0 = *(const float2*)&x[((size_t)b*CC + row0)*LL + colg];
        float2 xr1 = *(const float2*)&x[((size_t)b*CC + row1)*LL + colg];
        float v0 = acc[nt][0] + xr0.x, v1 = acc[nt][1] + xr0.y;
        float v2 = acc[nt][2] + xr1.x, v3 = acc[nt][3] + xr1.y;
        *(float2*)&g_x1[((size_t)b*CC + row0)*LL + colg] = make_float2(v0, v1);
        *(float2*)&g_x1[((size_t)b*CC + row1)*LL + colg] = make_float2(v2, v3);
        s += v0 + v1 + v2 + v3;
        ss += v0*v0 + v1*v1 + v2*v2 + v3*v3;
    }
    #pragma unroll
    for (int o = 16; o > 0; o >>= 1){
        s  += __shfl_down_sync(0xffffffffu, s,  o);
        ss += __shfl_down_sync(0xffffffffu, ss, o);
    }
    if (lane == 0){ rsw[wid] = s; rssw[wid] = ss; }
    __syncthreads();
    if (tid == 0){
        float a = 0.f, q = 0.f;
        for (int i = 0; i < 8; i++){ a += rsw[i]; q += rssw[i]; }
        g_part2[(b*128 + blockIdx.x)*2 + 0] = a;
        g_part2[(b*128 + blockIdx.x)*2 + 1] = q;
    }
}

// ---------------- GDFN pin ----------------
__global__ __launch_bounds__(256) void k_pin(const float* __restrict__ w){
    __shared__ unsigned Xs[64*XSTRIDE];
    int b = blockIdx.y;
    int l0 = blockIdx.x * 128;
    int tid = threadIdx.x;
    int wid = tid >> 5, lane = tid & 31;
    int gid = lane >> 2, tig = lane & 3;
    int m0 = (wid & 3) * 16, n0 = (wid >> 2) * 64;
    const float* scp = g_sc + (BB + b)*CC*2;
    for (int i = tid; i < 64*128; i += 256){
        int c = i >> 7, j = i & 127;
        Xs[c*XSTRIDE + j] = f2tf(fmaf(g_x1[((size_t)b*CC + c)*LL + l0 + j], scp[c*2], scp[c*2+1]));
    }
    __syncthreads();
    for (int og = 0; og < 6; og++){
        float acc[8][4];
        #pragma unroll
        for (int i = 0; i < 8; i++){ acc[i][0]=acc[i][1]=acc[i][2]=acc[i][3]=0.f; }
        int row0 = og*64 + m0 + gid, row1 = row0 + 8;
        #pragma unroll
        for (int kk = 0; kk < 8; kk++){
            int k0 = kk*8;
            int kcol = k0 + tig;
            unsigned a0 = (row0 < HID2) ? f2tf(w[row0*64 + kcol])     : 0u;
            unsigned a1 = (row1 < HID2) ? f2tf(w[row1*64 + kcol])     : 0u;
            unsigned a2 = (row0 < HID2) ? f2tf(w[row0*64 + kcol + 4]) : 0u;
            unsigned a3 = (row1 < HID2) ? f2tf(w[row1*64 + kcol + 4]) : 0u;
            mma8(acc, Xs, k0, n0, gid, tig, a0, a1, a2, a3);
        }
        #pragma unroll
        for (int nt = 0; nt < 8; nt++){
            int colg = l0 + n0 + nt*8 + 2*tig;
            if (row0 < HID2)
                *(unsigned*)&g_t[((size_t)b*HID2 + row0)*LL + colg] = pack_bf2(acc[nt][0], acc[nt][1]);
            if (row1 < HID2)
                *(unsigned*)&g_t[((size_t)b*HID2 + row1)*LL + colg] = pack_bf2(acc[nt][2], acc[nt][3]);
        }
    }
}

__global__ void k_dw(const float* __restrict__ dww){
    __shared__ float s1[10][34], s2[10][34];
    int bc = blockIdx.z;
    int b = bc / HIDc, ch = bc % HIDc;
    int w0 = blockIdx.x * 32, h0 = blockIdx.y * 8;
    int tid = threadIdx.y * 32 + threadIdx.x;
    const __nv_bfloat16* t1 = g_t + ((size_t)b*HID2 + ch)*LL;
    const __nv_bfloat16* t2 = g_t + ((size_t)b*HID2 + ch + HIDc)*LL;
    for (int idx = tid; idx < 10*34; idx += 256){
        int hh = idx / 34 - 1 + h0, ww = idx % 34 - 1 + w0;
        bool ok = (hh >= 0 && hh < HH && ww >= 0 && ww < WW);
        s1[idx/34][idx%34] = ok ? __bfloat162float(t1[hh*WW + ww]) : 0.f;
        s2[idx/34][idx%34] = ok ? __bfloat162float(t2[hh*WW + ww]) : 0.f;
    }
    __syncthreads();
    int th = threadIdx.y, tw = threadIdx.x;
    const float* w1 = dww + ch*9;
    const float* w2 = dww + (ch + HIDc)*9;
    float a1 = 0.f, a2 = 0.f;
    #pragma unroll
    for (int dy = 0; dy < 3; dy++)
        #pragma unroll
        for (int dx = 0; dx < 3; dx++){
            a1 = fmaf(w1[dy*3+dx], s1[th+dy][tw+dx], a1);
            a2 = fmaf(w2[dy*3+dx], s2[th+dy][tw+dx], a2);
        }
    g_gg[((size_t)b*HIDc + ch)*LL + (h0+th)*WW + w0+tw] =
        __float2bfloat16_rn(gelu_tanh(a1) * a2);
}

// ---------------- pout (+residual), double-buffered ----------------
__global__ __launch_bounds__(256) void k_pout(const float* __restrict__ w,
                                              float* __restrict__ out){
    __shared__ unsigned Xs[2*32*XSTRIDE];
    int b = blockIdx.y;
    int l0 = blockIdx.x * 128;
    int tid = threadIdx.x;
    int wid = tid >> 5, lane = tid & 31;
    int gid = lane >> 2, tig = lane & 3;
    int m0 = (wid & 3) * 16, n0 = (wid >> 2) * 64;
    int cth = tid >> 6;
    int jpth = (tid & 63) << 1;
    float acc[8][4];
    #pragma unroll
    for (int i = 0; i < 8; i++){ acc[i][0]=acc[i][1]=acc[i][2]=acc[i][3]=0.f; }
    int row0 = m0 + gid, row1 = m0 + gid + 8;
    unsigned ld[8];
    #pragma unroll
    for (int s = 0; s < 8; s++){
        int cg = cth + s*4;
        ld[s] = (cg < HIDc) ? *(const unsigned*)&g_gg[((size_t)b*HIDc + cg)*LL + l0 + jpth] : 0u;
    }
    int cur = 0;
    for (int kci = 0; kci < 6; kci++){
        int kc = kci*32;
        unsigned* Xb = Xs + cur*32*XSTRIDE;
        #pragma unroll
        for (int s = 0; s < 8; s++){
            int c = cth + s*4;
            Xb[c*XSTRIDE + jpth]     = bflo(ld[s]);
            Xb[c*XSTRIDE + jpth + 1] = bfhi(ld[s]);
        }
        __syncthreads();
        if (kci < 5){
            int kcn = kc + 32;
            #pragma unroll
            for (int s = 0; s < 8; s++){
                int cg = kcn + cth + s*4;
                ld[s] = (cg < HIDc) ? *(const unsigned*)&g_gg[((size_t)b*HIDc + cg)*LL + l0 + jpth] : 0u;
            }
        }
        #pragma unroll
        for (int kk = 0; kk < 4; kk++){
            int k0 = kk*8;
            int kcol = kc + k0 + tig;
            unsigned a0 = (kcol < HIDc)     ? f2tf(w[row0*HIDc + kcol])     : 0u;
            unsigned a1 = (kcol < HIDc)     ? f2tf(w[row1*HIDc + kcol])     : 0u;
            unsigned a2 = (kcol + 4 < HIDc) ? f2tf(w[row0*HIDc + kcol + 4]) : 0u;
            unsigned a3 = (kcol + 4 < HIDc) ? f2tf(w[row1*HIDc + kcol + 4]) : 0u;
            mma8(acc, Xb, k0, n0, gid, tig, a0, a1, a2, a3);
        }
        cur ^= 1;
    }
    #pragma unroll
    for (int nt = 0; nt < 8; nt++){
        int colg = l0 + n0 + nt*8 + 2*tig;
        float2 xr0 = *(const float2*)&g_x1[((size_t)b*CC + row0)*LL + colg];
        float2 xr1 = *(const float2*)&g_x1[((size_t)b*CC + row1)*LL + colg];
        *(float2*)&out[((size_t)b*CC + row0)*LL + colg] =
            make_float2(acc[nt][0] + xr0.x, acc[nt][1] + xr0.y);
        *(float2*)&out[((size_t)b*CC + row1)*LL + colg] =
            make_float2(acc[nt][2] + xr1.x, acc[nt][3] + xr1.y);
    }
}

extern "C" void kernel_launch(void* const* d_in, const int* in_sizes, int n_in,
                              void* d_out, int out_size){
    const float* x        = (const float*)d_in[0];
    const float* gn_a_g   = (const float*)d_in[1];
    const float* gn_a_b   = (const float*)d_in[2];
    const float* in_proj  = (const float*)d_in[3];
    const float* conv1d_w = (const float*)d_in[4];
    const float* conv1d_b = (const float*)d_in[5];
    const float* x_proj   = (const float*)d_in[6];
    const float* dt_w     = (const float*)d_in[7];
    const float* dt_b     = (const float*)d_in[8];
    const float* A_log    = (const float*)d_in[9];
    const float* D_param  = (const float*)d_in[10];
    const float* out_proj = (const float*)d_in[11];
    const float* attn_out = (const float*)d_in[12];
    const float* gn2_g    = (const float*)d_in[13];
    const float* gn2_b    = (const float*)d_in[14];
    const float* pin_w    = (const float*)d_in[15];
    const float* dw_w     = (const float*)d_in[16];
    const float* pout_w   = (const float*)d_in[17];
    float* out = (float*)d_out;

    const int SMEM_IPC = 64*XSTRIDE*4 + 128*132*4 + 64*4*4;
    cudaFuncSetAttribute(k_inprojconv, cudaFuncAttributeMaxDynamicSharedMemorySize, SMEM_IPC);

    k_stats1<<<dim3(256, BB), 256>>>(x);
    k_fin<<<BB, 256>>>(0, gn_a_g, gn_a_b);
    k_inprojconv<<<dim3(128, BB), 256, SMEM_IPC>>>(x, in_proj, conv1d_w, conv1d_b, x_proj);
    k_passA<<<dim3(NCHK, BB), 128>>>(A_log, dt_w, dt_b);
    k_passB<<<64, 64>>>();
    k_passC<<<dim3(NCHK, BB), 128>>>(A_log, dt_w, dt_b, D_param);
    k_Wc<<<32, 256>>>(attn_out, out_proj);
    k_outproj<<<dim3(128, BB), 256>>>(x);
    k_fin<<<BB, 256>>>(1, gn2_g, gn2_b);
    k_pin<<<dim3(128, BB), 256>>>(pin_w);
    k_dw<<<dim3(4, 16, BB*HIDc), dim3(32, 8)>>>(dw_w);
    k_pout<<<dim3(128, BB), 256>>>(pout_w, out);
}